// round 11
// baseline (speedup 1.0000x reference)
#include <cuda_runtime.h>
#include <cuda_bf16.h>
#include <cstddef>
#include <cstdint>

#define B_  8
#define L_  1024
#define H_  1024
#define K3_ 3072
#define N_  64

// ---------------------------------------------------------------------------
// Static scratch (no allocations allowed)
// ---------------------------------------------------------------------------
__device__ __align__(256) __nv_bfloat16 g_smp_hi[(size_t)B_ * L_ * K3_];
__device__ __align__(256) __nv_bfloat16 g_smp_lo[(size_t)B_ * L_ * K3_];
__device__ __align__(256) __nv_bfloat16 g_W_hi [(size_t)H_ * K3_];
__device__ __align__(256) __nv_bfloat16 g_W_lo [(size_t)H_ * K3_];
__device__ __align__(256) __nv_bfloat16 g_s_hi [(size_t)B_ * L_ * H_];  // later: A_hi
__device__ __align__(256) __nv_bfloat16 g_s_lo [(size_t)B_ * L_ * H_];  // later: A_lo
__device__ __align__(256) float g_A [(size_t)B_ * L_ * L_];             // graph (fp32)
__device__ __align__(256) float g_B0[(size_t)B_ * L_ * N_];
__device__ __align__(256) __nv_bfloat16 g_uh1[(size_t)B_ * L_ * N_];
__device__ __align__(256) __nv_bfloat16 g_ul1[(size_t)B_ * L_ * N_];
__device__ __align__(256) __nv_bfloat16 g_uh2[(size_t)B_ * L_ * N_];
__device__ __align__(256) __nv_bfloat16 g_ul2[(size_t)B_ * L_ * N_];

// ---------------------------------------------------------------------------
// PTX helpers (baseline-PTX only: cp.async / ldmatrix / mma.sync)
// ---------------------------------------------------------------------------
__device__ __forceinline__ uint32_t smem_u32(const void* p) {
    uint32_t a;
    asm("{ .reg .u64 t; cvta.to.shared.u64 t, %1; cvt.u32.u64 %0, t; }" : "=r"(a) : "l"(p));
    return a;
}

__device__ __forceinline__ void cp16(uint32_t saddr, const void* g) {
    asm volatile("cp.async.cg.shared.global [%0], [%1], 16;" :: "r"(saddr), "l"(g) : "memory");
}

__device__ __forceinline__ void ldsm4(uint32_t addr, uint32_t& r0, uint32_t& r1,
                                      uint32_t& r2, uint32_t& r3) {
    asm volatile("ldmatrix.sync.aligned.m8n8.x4.shared.b16 {%0,%1,%2,%3}, [%4];"
                 : "=r"(r0), "=r"(r1), "=r"(r2), "=r"(r3) : "r"(addr));
}

__device__ __forceinline__ void ldsm4t(uint32_t addr, uint32_t& r0, uint32_t& r1,
                                       uint32_t& r2, uint32_t& r3) {
    asm volatile("ldmatrix.sync.aligned.m8n8.x4.trans.shared.b16 {%0,%1,%2,%3}, [%4];"
                 : "=r"(r0), "=r"(r1), "=r"(r2), "=r"(r3) : "r"(addr));
}

__device__ __forceinline__ void mma16816(float* c, const uint32_t* a, const uint32_t* b) {
    asm volatile(
        "mma.sync.aligned.m16n8k16.row.col.f32.bf16.bf16.f32 "
        "{%0,%1,%2,%3}, {%4,%5,%6,%7}, {%8,%9}, {%0,%1,%2,%3};"
        : "+f"(c[0]), "+f"(c[1]), "+f"(c[2]), "+f"(c[3])
        : "r"(a[0]), "r"(a[1]), "r"(a[2]), "r"(a[3]), "r"(b[0]), "r"(b[1]));
}

// ---------------------------------------------------------------------------
// fp32 -> bf16 hi/lo split
// ---------------------------------------------------------------------------
__global__ __launch_bounds__(256)
void split_kernel(const float* __restrict__ x, __nv_bfloat16* __restrict__ hi,
                  __nv_bfloat16* __restrict__ lo, int n4)
{
    int i = blockIdx.x * blockDim.x + threadIdx.x;
    if (i >= n4) return;
    float4 v = ((const float4*)x)[i];
    __nv_bfloat16 h0 = __float2bfloat16(v.x), h1 = __float2bfloat16(v.y);
    __nv_bfloat16 h2 = __float2bfloat16(v.z), h3 = __float2bfloat16(v.w);
    float r0 = v.x - __bfloat162float(h0);
    float r1 = v.y - __bfloat162float(h1);
    float r2 = v.z - __bfloat162float(h2);
    float r3 = v.w - __bfloat162float(h3);
    uint2 hv, lv;
    hv.x = (uint32_t)__bfloat16_as_ushort(h0) | ((uint32_t)__bfloat16_as_ushort(h1) << 16);
    hv.y = (uint32_t)__bfloat16_as_ushort(h2) | ((uint32_t)__bfloat16_as_ushort(h3) << 16);
    __nv_bfloat162 l01 = __floats2bfloat162_rn(r0, r1);
    __nv_bfloat162 l23 = __floats2bfloat162_rn(r2, r3);
    lv.x = *reinterpret_cast<uint32_t*>(&l01);
    lv.y = *reinterpret_cast<uint32_t*>(&l23);
    ((uint2*)hi)[i] = hv;
    ((uint2*)lo)[i] = lv;
}

// ---------------------------------------------------------------------------
// Shared staging helper: (ITERS*64) rows x 32k bf16 tile, paired-row swizzle
// ---------------------------------------------------------------------------
template<int ITERS>
__device__ __forceinline__ void stage_rows(uint32_t sdst, const __nv_bfloat16* __restrict__ g,
                                           size_t row0, int ldk, int k0, int tid)
{
    #pragma unroll
    for (int i = 0; i < ITERS; i++) {
        int idx = tid + i * 256;
        int r = idx >> 2, c = idx & 3;
        const void* gp = g + (row0 + (size_t)r) * (size_t)ldk + k0 + c * 8;
        uint32_t line = (uint32_t)(r >> 1);
        uint32_t off = line * 128 + ((((uint32_t)(r & 1) * 4 + (uint32_t)c) ^ (line & 7)) << 4);
        cp16(sdst + off, gp);
    }
}

// ===========================================================================
// gemm_proj: s = samples @ W^T + bias -> bf16 hi/lo.
// Block 128(M) x 256(N), warp tile 64x64 (8 warps = 2x4), KC=32,
// 4-stage ring (192 KB) with top-of-stage early issue -> ~3-stage prefetch lead.
// ===========================================================================
#define P_ALO 8192
#define P_BHI 16384
#define P_BLO 32768
#define P_STG 49152
#define P_SMEM (4 * P_STG)

__global__ __launch_bounds__(256, 1)
void gemm_proj(const __nv_bfloat16* __restrict__ Ahi, const __nv_bfloat16* __restrict__ Alo,
               const __nv_bfloat16* __restrict__ Bhi, const __nv_bfloat16* __restrict__ Blo,
               const float* __restrict__ bias,
               __nv_bfloat16* __restrict__ Chi, __nv_bfloat16* __restrict__ Clo)
{
    extern __shared__ __align__(1024) char smem[];
    const uint32_t sb = smem_u32(smem);
    const int tid = threadIdx.x;
    const size_t row0 = (size_t)blockIdx.y * 128;
    const size_t col0 = (size_t)blockIdx.x * 256;
    const int K = K3_;

    const int lane = tid & 31, warp = tid >> 5;
    const int wm = warp >> 2, wn = warp & 3;

    const uint32_t dlA = (uint32_t)((lane & 15) >> 1);
    const uint32_t baseA = (uint32_t)(wm * 32 + dlA) * 128;
    uint32_t chA[2];
    #pragma unroll
    for (int ks = 0; ks < 2; ks++)
        chA[ks] = ((((uint32_t)(lane & 1) << 2) + (uint32_t)(2 * ks + (lane >> 4))) ^ dlA) << 4;
    const uint32_t vB  = (uint32_t)((lane & 7) | ((lane >> 4) << 3));
    const uint32_t dlB = vB >> 1;
    const uint32_t baseB = (uint32_t)(wn * 32 + dlB) * 128;
    uint32_t chB[2];
    #pragma unroll
    for (int ks = 0; ks < 2; ks++)
        chB[ks] = ((((uint32_t)(lane & 1) << 2) + (uint32_t)(2 * ks + ((lane >> 3) & 1))) ^ dlB) << 4;

    float acc[4][8][4];
    #pragma unroll
    for (int i = 0; i < 4; i++)
        #pragma unroll
        for (int j = 0; j < 8; j++)
            #pragma unroll
            for (int q = 0; q < 4; q++) acc[i][j][q] = 0.0f;

    const int NS = K / 32;
    // prologue: stages 0..2
    #pragma unroll
    for (int p = 0; p < 3; p++) {
        const uint32_t sp = sb + (uint32_t)p * P_STG;
        const int k0 = p * 32;
        stage_rows<2>(sp + 0,     Ahi, row0, K, k0, tid);
        stage_rows<2>(sp + P_ALO, Alo, row0, K, k0, tid);
        stage_rows<4>(sp + P_BHI, Bhi, col0, K, k0, tid);
        stage_rows<4>(sp + P_BLO, Blo, col0, K, k0, tid);
        asm volatile("cp.async.commit_group;" ::: "memory");
    }

    for (int st = 0; st < NS; st++) {
        if (st < NS - 2)       asm volatile("cp.async.wait_group 2;" ::: "memory");
        else if (st == NS - 2) asm volatile("cp.async.wait_group 1;" ::: "memory");
        else                   asm volatile("cp.async.wait_group 0;" ::: "memory");
        __syncthreads();
        // Early issue: barrier above guarantees all warps finished stage st-1
        // (which used buf[(st+3)&3]); safe to refill it now.
        if (st + 3 < NS) {
            const uint32_t np = sb + (uint32_t)((st + 3) & 3) * P_STG;
            const int k0 = (st + 3) * 32;
            stage_rows<2>(np + 0,     Ahi, row0, K, k0, tid);
            stage_rows<2>(np + P_ALO, Alo, row0, K, k0, tid);
            stage_rows<4>(np + P_BHI, Bhi, col0, K, k0, tid);
            stage_rows<4>(np + P_BLO, Blo, col0, K, k0, tid);
            asm volatile("cp.async.commit_group;" ::: "memory");
        }

        const uint32_t sbuf = sb + (uint32_t)(st & 3) * P_STG;
        #pragma unroll
        for (int ks = 0; ks < 2; ks++) {
            uint32_t ah[4][4], al[4][4];
            #pragma unroll
            for (int am = 0; am < 4; am++) {
                ldsm4(sbuf + baseA + am * 1024 + chA[ks],
                      ah[am][0], ah[am][1], ah[am][2], ah[am][3]);
                ldsm4(sbuf + P_ALO + baseA + am * 1024 + chA[ks],
                      al[am][0], al[am][1], al[am][2], al[am][3]);
            }
            uint32_t bh[8][2], bl[8][2];
            #pragma unroll
            for (int p = 0; p < 4; p++) {
                uint32_t r0, r1, r2, r3;
                ldsm4(sbuf + P_BHI + baseB + p * 1024 + chB[ks], r0, r1, r2, r3);
                bh[2 * p][0] = r0; bh[2 * p][1] = r1;
                bh[2 * p + 1][0] = r2; bh[2 * p + 1][1] = r3;
                ldsm4(sbuf + P_BLO + baseB + p * 1024 + chB[ks], r0, r1, r2, r3);
                bl[2 * p][0] = r0; bl[2 * p][1] = r1;
                bl[2 * p + 1][0] = r2; bl[2 * p + 1][1] = r3;
            }
            #pragma unroll
            for (int am = 0; am < 4; am++)
                #pragma unroll
                for (int an = 0; an < 8; an++) {
                    mma16816(acc[am][an], ah[am], bh[an]);
                    mma16816(acc[am][an], ah[am], bl[an]);
                    mma16816(acc[am][an], al[am], bh[an]);
                }
        }
    }

    const int re = (int)row0 + wm * 64 + (lane >> 2);
    const int ce = (int)col0 + wn * 64 + (lane & 3) * 2;
    #pragma unroll
    for (int am = 0; am < 4; am++) {
        #pragma unroll
        for (int an = 0; an < 8; an++) {
            const int r = re + am * 16;
            const int c = ce + an * 8;
            float v0 = acc[am][an][0] + bias[c];
            float v1 = acc[am][an][1] + bias[c + 1];
            float v2 = acc[am][an][2] + bias[c];
            float v3 = acc[am][an][3] + bias[c + 1];
            __nv_bfloat16 h0 = __float2bfloat16(v0), h1 = __float2bfloat16(v1);
            __nv_bfloat16 h2 = __float2bfloat16(v2), h3 = __float2bfloat16(v3);
            __nv_bfloat162 lp0 = __floats2bfloat162_rn(v0 - __bfloat162float(h0),
                                                       v1 - __bfloat162float(h1));
            __nv_bfloat162 lp1 = __floats2bfloat162_rn(v2 - __bfloat162float(h2),
                                                       v3 - __bfloat162float(h3));
            uint32_t hp0 = (uint32_t)__bfloat16_as_ushort(h0) |
                           ((uint32_t)__bfloat16_as_ushort(h1) << 16);
            uint32_t hp1 = (uint32_t)__bfloat16_as_ushort(h2) |
                           ((uint32_t)__bfloat16_as_ushort(h3) << 16);
            *(uint32_t*)&Chi[(size_t)r * H_ + c]       = hp0;
            *(uint32_t*)&Chi[(size_t)(r + 8) * H_ + c] = hp1;
            *(uint32_t*)&Clo[(size_t)r * H_ + c]       = *reinterpret_cast<uint32_t*>(&lp0);
            *(uint32_t*)&Clo[(size_t)(r + 8) * H_ + c] = *reinterpret_cast<uint32_t*>(&lp1);
        }
    }
}

// ===========================================================================
// gemm_sym: graph[b] = s[b] @ s[b]^T (fp32), upper-tri tiles + mirror write.
// Block 128x128, warp 64x32, KC=32, 3-stage ring, 2 CTAs/SM.  (unchanged R10)
// ===========================================================================
#define S_ALO 8192
#define S_BHI 16384
#define S_BLO 24576
#define S_STG 32768
#define S_SMEM (3 * S_STG)

__global__ __launch_bounds__(256, 2)
void gemm_sym(const __nv_bfloat16* __restrict__ sh, const __nv_bfloat16* __restrict__ sl,
              float* __restrict__ G)
{
    extern __shared__ __align__(1024) char smem[];
    const uint32_t sb = smem_u32(smem);
    const int tid = threadIdx.x;
    const int bz  = blockIdx.z;
    const int K = H_;

    int by = 0, rem = blockIdx.x;
    #pragma unroll
    for (int i = 0; i < 8; i++) {
        if (rem >= 8 - by) { rem -= (8 - by); by++; }
    }
    const int bx = by + rem;

    const __nv_bfloat16* Ahi = sh + (size_t)bz * L_ * H_;
    const __nv_bfloat16* Alo = sl + (size_t)bz * L_ * H_;
    float* Gb = G + (size_t)bz * L_ * L_;

    const size_t row0 = (size_t)by * 128;
    const size_t col0 = (size_t)bx * 128;

    const int lane = tid & 31, warp = tid >> 5;
    const int wm = warp >> 2, wn = warp & 3;

    const uint32_t dlA = (uint32_t)((lane & 15) >> 1);
    const uint32_t baseA = (uint32_t)(wm * 32 + dlA) * 128;
    uint32_t chA[2];
    #pragma unroll
    for (int ks = 0; ks < 2; ks++)
        chA[ks] = ((((uint32_t)(lane & 1) << 2) + (uint32_t)(2 * ks + (lane >> 4))) ^ dlA) << 4;
    const uint32_t vB  = (uint32_t)((lane & 7) | ((lane >> 4) << 3));
    const uint32_t dlB = vB >> 1;
    const uint32_t baseB = (uint32_t)(wn * 16 + dlB) * 128;
    uint32_t chB[2];
    #pragma unroll
    for (int ks = 0; ks < 2; ks++)
        chB[ks] = ((((uint32_t)(lane & 1) << 2) + (uint32_t)(2 * ks + ((lane >> 3) & 1))) ^ dlB) << 4;

    float acc[4][4][4];
    #pragma unroll
    for (int i = 0; i < 4; i++)
        #pragma unroll
        for (int j = 0; j < 4; j++)
            #pragma unroll
            for (int q = 0; q < 4; q++) acc[i][j][q] = 0.0f;

    const int NS = K / 32;
    {
        uint32_t s0 = sb, s1 = sb + S_STG;
        stage_rows<2>(s0 + 0,     Ahi, row0, K, 0, tid);
        stage_rows<2>(s0 + S_ALO, Alo, row0, K, 0, tid);
        stage_rows<2>(s0 + S_BHI, Ahi, col0, K, 0, tid);
        stage_rows<2>(s0 + S_BLO, Alo, col0, K, 0, tid);
        asm volatile("cp.async.commit_group;" ::: "memory");
        stage_rows<2>(s1 + 0,     Ahi, row0, K, 32, tid);
        stage_rows<2>(s1 + S_ALO, Alo, row0, K, 32, tid);
        stage_rows<2>(s1 + S_BHI, Ahi, col0, K, 32, tid);
        stage_rows<2>(s1 + S_BLO, Alo, col0, K, 32, tid);
        asm volatile("cp.async.commit_group;" ::: "memory");
    }

    int buf = 0;
    for (int st = 0; st < NS; st++) {
        if (st + 1 < NS) asm volatile("cp.async.wait_group 1;" ::: "memory");
        else             asm volatile("cp.async.wait_group 0;" ::: "memory");
        __syncthreads();

        const uint32_t sbuf = sb + (uint32_t)buf * S_STG;
        #pragma unroll
        for (int ks = 0; ks < 2; ks++) {
            uint32_t ah[4][4], al[4][4];
            #pragma unroll
            for (int am = 0; am < 4; am++) {
                ldsm4(sbuf + baseA + am * 1024 + chA[ks],
                      ah[am][0], ah[am][1], ah[am][2], ah[am][3]);
                ldsm4(sbuf + S_ALO + baseA + am * 1024 + chA[ks],
                      al[am][0], al[am][1], al[am][2], al[am][3]);
            }
            uint32_t bh[4][2], bl[4][2];
            #pragma unroll
            for (int p = 0; p < 2; p++) {
                uint32_t r0, r1, r2, r3;
                ldsm4(sbuf + S_BHI + baseB + p * 1024 + chB[ks], r0, r1, r2, r3);
                bh[2 * p][0] = r0; bh[2 * p][1] = r1;
                bh[2 * p + 1][0] = r2; bh[2 * p + 1][1] = r3;
                ldsm4(sbuf + S_BLO + baseB + p * 1024 + chB[ks], r0, r1, r2, r3);
                bl[2 * p][0] = r0; bl[2 * p][1] = r1;
                bl[2 * p + 1][0] = r2; bl[2 * p + 1][1] = r3;
            }
            #pragma unroll
            for (int am = 0; am < 4; am++)
                #pragma unroll
                for (int an = 0; an < 4; an++) {
                    mma16816(acc[am][an], ah[am], bh[an]);
                    mma16816(acc[am][an], ah[am], bl[an]);
                    mma16816(acc[am][an], al[am], bh[an]);
                }
        }

        if (st + 2 < NS) {
            int nb = buf + 2; if (nb >= 3) nb -= 3;
            const uint32_t np = sb + (uint32_t)nb * S_STG;
            const int k0 = (st + 2) * 32;
            stage_rows<2>(np + 0,     Ahi, row0, K, k0, tid);
            stage_rows<2>(np + S_ALO, Alo, row0, K, k0, tid);
            stage_rows<2>(np + S_BHI, Ahi, col0, K, k0, tid);
            stage_rows<2>(np + S_BLO, Alo, col0, K, k0, tid);
            asm volatile("cp.async.commit_group;" ::: "memory");
        }
        if (++buf == 3) buf = 0;
    }

    // all warps must finish reading the smem ring before it is reused below
    __syncthreads();

    const int rl = wm * 64 + (lane >> 2);
    const int cl = wn * 32 + (lane & 3) * 2;
    float* eb = (float*)smem;     // 128 x 129 fp32 staging
    #pragma unroll
    for (int am = 0; am < 4; am++) {
        #pragma unroll
        for (int an = 0; an < 4; an++) {
            const int r = rl + am * 16;
            const int c = cl + an * 8;
            float v0 = acc[am][an][0], v1 = acc[am][an][1];
            float v2 = acc[am][an][2], v3 = acc[am][an][3];
            *(float2*)&Gb[(row0 + r) * L_ + col0 + c]     = make_float2(v0, v1);
            *(float2*)&Gb[(row0 + r + 8) * L_ + col0 + c] = make_float2(v2, v3);
            if (bx != by) {
                eb[r * 129 + c] = v0;       eb[r * 129 + c + 1] = v1;
                eb[(r + 8) * 129 + c] = v2; eb[(r + 8) * 129 + c + 1] = v3;
            }
        }
    }
    if (bx != by) {
        __syncthreads();
        #pragma unroll 4
        for (int it = 0; it < 64; it++) {
            int idx = tid + it * 256;
            int j = idx >> 7, i = idx & 127;
            Gb[(col0 + j) * L_ + row0 + i] = eb[i * 129 + j];
        }
    }
}

// ---------------------------------------------------------------------------
// Row softmax, diag masked; emits A as bf16 hi/lo.
// ---------------------------------------------------------------------------
__global__ __launch_bounds__(256)
void softmax_kernel(const float* __restrict__ G, __nv_bfloat16* __restrict__ Ah,
                    __nv_bfloat16* __restrict__ Al)
{
    const int l = blockIdx.x;
    const int b = blockIdx.y;
    const size_t rowoff = ((size_t)b * L_ + (size_t)l) * L_;
    const int tid = threadIdx.x;

    float4 v = ((const float4*)(G + rowoff))[tid];
    if ((l >> 2) == tid) (&v.x)[l & 3] -= 1e5f;

    float mx = fmaxf(fmaxf(v.x, v.y), fmaxf(v.z, v.w));

    __shared__ float red1[8];
    __shared__ float red2[8];
    #pragma unroll
    for (int o = 16; o > 0; o >>= 1)
        mx = fmaxf(mx, __shfl_xor_sync(0xffffffffu, mx, o));
    if ((tid & 31) == 0) red1[tid >> 5] = mx;
    __syncthreads();
    mx = red1[0];
    #pragma unroll
    for (int i = 1; i < 8; i++) mx = fmaxf(mx, red1[i]);

    v.x = __expf(v.x - mx); v.y = __expf(v.y - mx);
    v.z = __expf(v.z - mx); v.w = __expf(v.w - mx);
    float s = (v.x + v.y) + (v.z + v.w);
    #pragma unroll
    for (int o = 16; o > 0; o >>= 1)
        s += __shfl_xor_sync(0xffffffffu, s, o);
    if ((tid & 31) == 0) red2[tid >> 5] = s;
    __syncthreads();
    s = red2[0];
    #pragma unroll
    for (int i = 1; i < 8; i++) s += red2[i];

    const float inv = 1.0f / s;
    v.x *= inv; v.y *= inv; v.z *= inv; v.w *= inv;

    __nv_bfloat16 h0 = __float2bfloat16(v.x), h1 = __float2bfloat16(v.y);
    __nv_bfloat16 h2 = __float2bfloat16(v.z), h3 = __float2bfloat16(v.w);
    float l0 = v.x - __bfloat162float(h0);
    float l1 = v.y - __bfloat162float(h1);
    float l2 = v.z - __bfloat162float(h2);
    float l3 = v.w - __bfloat162float(h3);
    uint2 hv, lv;
    hv.x = (uint32_t)__bfloat16_as_ushort(h0) | ((uint32_t)__bfloat16_as_ushort(h1) << 16);
    hv.y = (uint32_t)__bfloat16_as_ushort(h2) | ((uint32_t)__bfloat16_as_ushort(h3) << 16);
    __nv_bfloat162 p01 = __floats2bfloat162_rn(l0, l1);
    __nv_bfloat162 p23 = __floats2bfloat162_rn(l2, l3);
    lv.x = *reinterpret_cast<uint32_t*>(&p01);
    lv.y = *reinterpret_cast<uint32_t*>(&p23);
    ((uint2*)(Ah + rowoff))[tid] = hv;
    ((uint2*)(Al + rowoff))[tid] = lv;
}

// ---------------------------------------------------------------------------
// B0 = (sup - colsum/total) * row_has (fp32);  u1 = B0 as bf16 hi/lo.
// ---------------------------------------------------------------------------
__global__ __launch_bounds__(1024)
void b0_kernel(const float* __restrict__ lab, float* __restrict__ B0,
               __nv_bfloat16* __restrict__ uh, __nv_bfloat16* __restrict__ ul)
{
    const int b = blockIdx.x;
    const int t = threadIdx.x;
    const float* supb = lab + (size_t)b * L_ * N_;

    __shared__ float colp[16][64];
    __shared__ float s_col[64];
    __shared__ float s_rh[L_];
    __shared__ float s_tot;

    if (t == 0) s_tot = 0.0f;

    {
        const int c = t & 63, g = t >> 6;
        float cp = 0.0f;
        #pragma unroll 4
        for (int i = 0; i < 64; i++)
            cp += supb[(size_t)(i * 16 + g) * N_ + c];
        colp[g][c] = cp;
    }
    {
        const int w = t >> 5, lane = t & 31;
        for (int r = w; r < L_; r += 32) {
            float v = supb[(size_t)r * N_ + lane] + supb[(size_t)r * N_ + 32 + lane];
            #pragma unroll
            for (int o = 16; o > 0; o >>= 1) v += __shfl_xor_sync(0xffffffffu, v, o);
            if (lane == 0) s_rh[r] = (v > 0.5f) ? 1.0f : 0.0f;
        }
    }
    __syncthreads();
    if (t < 64) {
        float s = 0.0f;
        #pragma unroll
        for (int j = 0; j < 16; j++) s += colp[j][t];
        s_col[t] = s;
    }
    {
        float v = s_rh[t];
        #pragma unroll
        for (int o = 16; o > 0; o >>= 1) v += __shfl_xor_sync(0xffffffffu, v, o);
        if ((t & 31) == 0) atomicAdd(&s_tot, v);
    }
    __syncthreads();

    const float inv = 1.0f / s_tot;
    const size_t boff = (size_t)b * L_ * N_;
    #pragma unroll 4
    for (int i = 0; i < 64; i++) {
        const int idx = t + i * 1024;
        const int r = idx >> 6, n = idx & 63;
        float v = (supb[idx] - s_col[n] * inv) * s_rh[r];
        B0[boff + idx] = v;
        __nv_bfloat16 h = __float2bfloat16(v);
        uh[boff + idx] = h;
        ul[boff + idx] = __float2bfloat16(v - __bfloat162float(h));
    }
}

// ---------------------------------------------------------------------------
// Tensor-core power-iteration step — now 4-stage ring with early issue.
// ---------------------------------------------------------------------------
#define IT_KC   32
#define IT_AL_OFF 8192
#define IT_UH_OFF 16384
#define IT_UL_OFF 20480
#define IT_STG  24576
#define IT_SMEM (4 * IT_STG)

__device__ __forceinline__ void it_stage(uint32_t sbuf,
        const __nv_bfloat16* __restrict__ Ah, const __nv_bfloat16* __restrict__ Al,
        const __nv_bfloat16* __restrict__ uh, const __nv_bfloat16* __restrict__ ul,
        int l0, int k0, int tid)
{
    #pragma unroll
    for (int i = 0; i < 2; i++) {
        int idx = tid + i * 256;
        int r = idx >> 4, c = idx & 15;
        uint32_t off = (uint32_t)r * 256 + ((uint32_t)(c ^ (r & 15)) << 4);
        const void* gp = Ah + (size_t)(k0 + r) * L_ + l0 + c * 8;
        cp16(sbuf + off, gp);
        const void* gq = Al + (size_t)(k0 + r) * L_ + l0 + c * 8;
        cp16(sbuf + IT_AL_OFF + off, gq);
    }
    {
        int r = tid >> 3, c = tid & 7;
        uint32_t off = (uint32_t)r * 128 + ((uint32_t)(c ^ (r & 7)) << 4);
        cp16(sbuf + IT_UH_OFF + off, uh + (size_t)(k0 + r) * N_ + c * 8);
        cp16(sbuf + IT_UL_OFF + off, ul + (size_t)(k0 + r) * N_ + c * 8);
    }
    asm volatile("cp.async.commit_group;" ::: "memory");
}

template<int LAST>
__global__ __launch_bounds__(256, 2)
void iter_mma(const __nv_bfloat16* __restrict__ Ah, const __nv_bfloat16* __restrict__ Al,
              const __nv_bfloat16* __restrict__ uh_in, const __nv_bfloat16* __restrict__ ul_in,
              const float* __restrict__ B0, const float* __restrict__ pred,
              __nv_bfloat16* __restrict__ uh_out, __nv_bfloat16* __restrict__ ul_out,
              float* __restrict__ f32out)
{
    extern __shared__ __align__(1024) char smem[];
    const uint32_t sb = smem_u32(smem);
    const int tid = threadIdx.x;
    const int b = blockIdx.z;
    const int l0 = blockIdx.x * 128;

    const __nv_bfloat16* Ahb = Ah + (size_t)b * L_ * L_;
    const __nv_bfloat16* Alb = Al + (size_t)b * L_ * L_;
    const __nv_bfloat16* uhb = uh_in + (size_t)b * L_ * N_;
    const __nv_bfloat16* ulb = ul_in + (size_t)b * L_ * N_;

    const int lane = tid & 31, warp = tid >> 5;
    const int wm = warp >> 2, wn = warp & 3;

    uint32_t aoff[2][4];
    {
        uint32_t k_lane = (uint32_t)((lane & 7) + ((lane >> 4) << 3));
        uint32_t mbit = (uint32_t)((lane >> 3) & 1);
        #pragma unroll
        for (int ks = 0; ks < 2; ks++) {
            uint32_t k = (uint32_t)(ks * 16) + k_lane;
            #pragma unroll
            for (int am = 0; am < 4; am++) {
                uint32_t cA = (uint32_t)(wm * 8 + am * 2) + mbit;
                aoff[ks][am] = k * 256 + ((cA ^ (k & 15)) << 4);
            }
        }
    }
    uint32_t uoff[2];
    {
        uint32_t k_lane = (uint32_t)((lane & 7) + (((lane >> 3) & 1) << 3));
        uint32_t cn = (uint32_t)(wn * 2 + (lane >> 4));
        #pragma unroll
        for (int ks = 0; ks < 2; ks++) {
            uint32_t k = (uint32_t)(ks * 16) + k_lane;
            uoff[ks] = k * 128 + ((cn ^ (k & 7)) << 4);
        }
    }

    float acc[4][2][4];
    #pragma unroll
    for (int i = 0; i < 4; i++)
        #pragma unroll
        for (int j = 0; j < 2; j++)
            #pragma unroll
            for (int q = 0; q < 4; q++) acc[i][j][q] = 0.0f;

    const int NS = L_ / IT_KC;   // 32
    // prologue: stages 0..2
    it_stage(sb + 0 * IT_STG, Ahb, Alb, uhb, ulb, l0, 0 * IT_KC, tid);
    it_stage(sb + 1 * IT_STG, Ahb, Alb, uhb, ulb, l0, 1 * IT_KC, tid);
    it_stage(sb + 2 * IT_STG, Ahb, Alb, uhb, ulb, l0, 2 * IT_KC, tid);

    for (int st = 0; st < NS; st++) {
        if (st < NS - 2)       asm volatile("cp.async.wait_group 2;" ::: "memory");
        else if (st == NS - 2) asm volatile("cp.async.wait_group 1;" ::: "memory");
        else                   asm volatile("cp.async.wait_group 0;" ::: "memory");
        __syncthreads();
        if (st + 3 < NS)
            it_stage(sb + (uint32_t)((st + 3) & 3) * IT_STG, Ahb, Alb, uhb, ulb,
                     l0, (st + 3) * IT_KC, tid);

        const uint32_t sbuf = sb + (uint32_t)(st & 3) * IT_STG;
        #pragma unroll
        for (int ks = 0; ks < 2; ks++) {
            uint32_t ah[4][4], al4[4][4];
            #pragma unroll
            for (int am = 0; am < 4; am++) {
                ldsm4t(sbuf + aoff[ks][am],
                       ah[am][0], ah[am][1], ah[am][2], ah[am][3]);
                ldsm4t(sbuf + IT_AL_OFF + aoff[ks][am],
                       al4[am][0], al4[am][1], al4[am][2], al4[am][3]);
            }
            uint32_t bh[2][2], bl[2][2];
            {
                uint32_t r0, r1, r2, r3;
                ldsm4t(sbuf + IT_UH_OFF + uoff[ks], r0, r1, r2, r3);
                bh[0][0] = r0; bh[0][1] = r1; bh[1][0] = r2; bh[1][1] = r3;
                ldsm4t(sbuf + IT_UL_OFF + uoff[ks], r0, r1, r2, r3);
                bl[0][0] = r0; bl[0][1] = r1; bl[1][0] = r2; bl[1][1] = r3;
            }
            #pragma unroll
            for (int am = 0; am < 4; am++)
                #pragma unroll
                for (int an = 0; an < 2; an++) {
                    mma16816(acc[am][an], ah[am], bh[an]);
                    mma16816(acc[am][an], ah[am], bl[an]);
                    mma16816(acc[am][an], al4[am], bh[an]);
                }
        }
    }

    const int lbase = l0 + wm * 64 + (lane >> 2);
    const int nbase = wn * 16 + (lane & 3) * 2;
    #pragma unroll
    for (int am = 0; am < 4; am++) {
        #pragma unroll
        for (int an = 0; an < 2; an++) {
            const int l = lbase + am * 16;
            const int n = nbase + an * 8;
            const size_t o0 = ((size_t)b * L_ + l) * N_ + n;
            const size_t o1 = o0 + 8 * N_;
            float v0 = acc[am][an][0] + B0[o0];
            float v1 = acc[am][an][1] + B0[o0 + 1];
            float v2 = acc[am][an][2] + B0[o1];
            float v3 = acc[am][an][3] + B0[o1 + 1];
            if (pred) {
                v0 += pred[o0]; v1 += pred[o0 + 1];
                v2 += pred[o1]; v3 += pred[o1 + 1];
            }
            if (LAST) {
                *(float2*)&f32out[o0] = make_float2(v0, v1);
                *(float2*)&f32out[o1] = make_float2(v2, v3);
            } else {
                __nv_bfloat16 h0 = __float2bfloat16(v0), h1 = __float2bfloat16(v1);
                __nv_bfloat16 h2 = __float2bfloat16(v2), h3 = __float2bfloat16(v3);
                __nv_bfloat162 lo01 = __floats2bfloat162_rn(v0 - __bfloat162float(h0),
                                                            v1 - __bfloat162float(h1));
                __nv_bfloat162 lo23 = __floats2bfloat162_rn(v2 - __bfloat162float(h2),
                                                            v3 - __bfloat162float(h3));
                uint32_t hp0 = (uint32_t)__bfloat16_as_ushort(h0) |
                               ((uint32_t)__bfloat16_as_ushort(h1) << 16);
                uint32_t hp1 = (uint32_t)__bfloat16_as_ushort(h2) |
                               ((uint32_t)__bfloat16_as_ushort(h3) << 16);
                *(uint32_t*)&uh_out[o0] = hp0;
                *(uint32_t*)&uh_out[o1] = hp1;
                *(uint32_t*)&ul_out[o0] = *reinterpret_cast<uint32_t*>(&lo01);
                *(uint32_t*)&ul_out[o1] = *reinterpret_cast<uint32_t*>(&lo23);
            }
        }
    }
}

// ---------------------------------------------------------------------------
extern "C" void kernel_launch(void* const* d_in, const int* in_sizes, int n_in,
                              void* d_out, int out_size)
{
    const float* samples = (const float*)d_in[0];  // [8,1024,3072]
    const float* label   = (const float*)d_in[1];  // [8,1024,64]
    const float* predict = (const float*)d_in[2];  // [8,1024,64]
    const float* W       = (const float*)d_in[3];  // [1024,3072]
    const float* bproj   = (const float*)d_in[4];  // [1024]
    float* out = (float*)d_out;                    // [8,1024,64]

    __nv_bfloat16 *smph, *smpl, *Wh, *Wl, *sh, *sl, *uh1, *ul1, *uh2, *ul2;
    float *A, *B0;
    cudaGetSymbolAddress((void**)&smph, g_smp_hi);
    cudaGetSymbolAddress((void**)&smpl, g_smp_lo);
    cudaGetSymbolAddress((void**)&Wh,   g_W_hi);
    cudaGetSymbolAddress((void**)&Wl,   g_W_lo);
    cudaGetSymbolAddress((void**)&sh,   g_s_hi);
    cudaGetSymbolAddress((void**)&sl,   g_s_lo);
    cudaGetSymbolAddress((void**)&A,    g_A);
    cudaGetSymbolAddress((void**)&B0,   g_B0);
    cudaGetSymbolAddress((void**)&uh1,  g_uh1);
    cudaGetSymbolAddress((void**)&ul1,  g_ul1);
    cudaGetSymbolAddress((void**)&uh2,  g_uh2);
    cudaGetSymbolAddress((void**)&ul2,  g_ul2);

    cudaFuncSetAttribute(gemm_proj, cudaFuncAttributeMaxDynamicSharedMemorySize, P_SMEM);
    cudaFuncSetAttribute(gemm_sym,  cudaFuncAttributeMaxDynamicSharedMemorySize, S_SMEM);
    cudaFuncSetAttribute(iter_mma<0>, cudaFuncAttributeMaxDynamicSharedMemorySize, IT_SMEM);
    cudaFuncSetAttribute(iter_mma<1>, cudaFuncAttributeMaxDynamicSharedMemorySize, IT_SMEM);

    {
        int n4 = (B_ * L_ * K3_) / 4;
        split_kernel<<<(n4 + 255) / 256, 256>>>(samples, smph, smpl, n4);
        int w4 = (H_ * K3_) / 4;
        split_kernel<<<(w4 + 255) / 256, 256>>>(W, Wh, Wl, w4);
    }

    gemm_proj<<<dim3(H_ / 256, (B_ * L_) / 128, 1), 256, P_SMEM>>>(
        smph, smpl, Wh, Wl, bproj, sh, sl);

    gemm_sym<<<dim3(36, 1, B_), 256, S_SMEM>>>(sh, sl, A);

    softmax_kernel<<<dim3(L_, B_), 256>>>(A, sh, sl);

    b0_kernel<<<B_, 1024>>>(label, B0, uh1, ul1);

    dim3 ig(L_ / 128, 1, B_);
    iter_mma<0><<<ig, 256, IT_SMEM>>>(sh, sl, uh1, ul1, B0, nullptr,  uh2, ul2, nullptr); // t=2
    iter_mma<0><<<ig, 256, IT_SMEM>>>(sh, sl, uh2, ul2, B0, predict,  uh1, ul1, nullptr); // t=3
    iter_mma<0><<<ig, 256, IT_SMEM>>>(sh, sl, uh1, ul1, B0, nullptr,  uh2, ul2, nullptr); // t=4
    iter_mma<0><<<ig, 256, IT_SMEM>>>(sh, sl, uh2, ul2, B0, nullptr,  uh1, ul1, nullptr); // t=5
    iter_mma<1><<<ig, 256, IT_SMEM>>>(sh, sl, uh1, ul1, B0, nullptr,  nullptr, nullptr, out); // t=6
}

// round 12
// speedup vs baseline: 1.0202x; 1.0202x over previous
#include <cuda_runtime.h>
#include <cuda_bf16.h>
#include <cstddef>
#include <cstdint>

#define B_  8
#define L_  1024
#define H_  1024
#define K3_ 3072
#define N_  64

// ---------------------------------------------------------------------------
// Static scratch (no allocations allowed)
// ---------------------------------------------------------------------------
__device__ __align__(256) __nv_bfloat16 g_smp_hi[(size_t)B_ * L_ * K3_];
__device__ __align__(256) __nv_bfloat16 g_smp_lo[(size_t)B_ * L_ * K3_];
__device__ __align__(256) __nv_bfloat16 g_W_hi [(size_t)H_ * K3_];
__device__ __align__(256) __nv_bfloat16 g_W_lo [(size_t)H_ * K3_];
__device__ __align__(256) __nv_bfloat16 g_s_hi [(size_t)B_ * L_ * H_];  // later: A_hi
__device__ __align__(256) __nv_bfloat16 g_s_lo [(size_t)B_ * L_ * H_];  // later: A_lo
__device__ __align__(256) float g_A [(size_t)B_ * L_ * L_];             // graph (fp32)
__device__ __align__(256) float g_B0[(size_t)B_ * L_ * N_];
__device__ __align__(256) __nv_bfloat16 g_uh1[(size_t)B_ * L_ * N_];
__device__ __align__(256) __nv_bfloat16 g_ul1[(size_t)B_ * L_ * N_];
__device__ __align__(256) __nv_bfloat16 g_uh2[(size_t)B_ * L_ * N_];
__device__ __align__(256) __nv_bfloat16 g_ul2[(size_t)B_ * L_ * N_];

// ---------------------------------------------------------------------------
// PTX helpers (baseline-PTX only: cp.async / ldmatrix / mma.sync)
// ---------------------------------------------------------------------------
__device__ __forceinline__ uint32_t smem_u32(const void* p) {
    uint32_t a;
    asm("{ .reg .u64 t; cvta.to.shared.u64 t, %1; cvt.u32.u64 %0, t; }" : "=r"(a) : "l"(p));
    return a;
}

__device__ __forceinline__ void cp16(uint32_t saddr, const void* g) {
    asm volatile("cp.async.cg.shared.global [%0], [%1], 16;" :: "r"(saddr), "l"(g) : "memory");
}

__device__ __forceinline__ void ldsm4(uint32_t addr, uint32_t& r0, uint32_t& r1,
                                      uint32_t& r2, uint32_t& r3) {
    asm volatile("ldmatrix.sync.aligned.m8n8.x4.shared.b16 {%0,%1,%2,%3}, [%4];"
                 : "=r"(r0), "=r"(r1), "=r"(r2), "=r"(r3) : "r"(addr));
}

__device__ __forceinline__ void ldsm4t(uint32_t addr, uint32_t& r0, uint32_t& r1,
                                       uint32_t& r2, uint32_t& r3) {
    asm volatile("ldmatrix.sync.aligned.m8n8.x4.trans.shared.b16 {%0,%1,%2,%3}, [%4];"
                 : "=r"(r0), "=r"(r1), "=r"(r2), "=r"(r3) : "r"(addr));
}

__device__ __forceinline__ void mma16816(float* c, const uint32_t* a, const uint32_t* b) {
    asm volatile(
        "mma.sync.aligned.m16n8k16.row.col.f32.bf16.bf16.f32 "
        "{%0,%1,%2,%3}, {%4,%5,%6,%7}, {%8,%9}, {%0,%1,%2,%3};"
        : "+f"(c[0]), "+f"(c[1]), "+f"(c[2]), "+f"(c[3])
        : "r"(a[0]), "r"(a[1]), "r"(a[2]), "r"(a[3]), "r"(b[0]), "r"(b[1]));
}

// ---------------------------------------------------------------------------
// fp32 -> bf16 hi/lo split
// ---------------------------------------------------------------------------
__global__ __launch_bounds__(256)
void split_kernel(const float* __restrict__ x, __nv_bfloat16* __restrict__ hi,
                  __nv_bfloat16* __restrict__ lo, int n4)
{
    int i = blockIdx.x * blockDim.x + threadIdx.x;
    if (i >= n4) return;
    float4 v = ((const float4*)x)[i];
    __nv_bfloat16 h0 = __float2bfloat16(v.x), h1 = __float2bfloat16(v.y);
    __nv_bfloat16 h2 = __float2bfloat16(v.z), h3 = __float2bfloat16(v.w);
    float r0 = v.x - __bfloat162float(h0);
    float r1 = v.y - __bfloat162float(h1);
    float r2 = v.z - __bfloat162float(h2);
    float r3 = v.w - __bfloat162float(h3);
    uint2 hv, lv;
    hv.x = (uint32_t)__bfloat16_as_ushort(h0) | ((uint32_t)__bfloat16_as_ushort(h1) << 16);
    hv.y = (uint32_t)__bfloat16_as_ushort(h2) | ((uint32_t)__bfloat16_as_ushort(h3) << 16);
    __nv_bfloat162 l01 = __floats2bfloat162_rn(r0, r1);
    __nv_bfloat162 l23 = __floats2bfloat162_rn(r2, r3);
    lv.x = *reinterpret_cast<uint32_t*>(&l01);
    lv.y = *reinterpret_cast<uint32_t*>(&l23);
    ((uint2*)hi)[i] = hv;
    ((uint2*)lo)[i] = lv;
}

// ---------------------------------------------------------------------------
// Shared staging helper: (ITERS*64) rows x 32k bf16 tile, paired-row swizzle
// ---------------------------------------------------------------------------
template<int ITERS>
__device__ __forceinline__ void stage_rows(uint32_t sdst, const __nv_bfloat16* __restrict__ g,
                                           size_t row0, int ldk, int k0, int tid)
{
    #pragma unroll
    for (int i = 0; i < ITERS; i++) {
        int idx = tid + i * 256;
        int r = idx >> 2, c = idx & 3;
        const void* gp = g + (row0 + (size_t)r) * (size_t)ldk + k0 + c * 8;
        uint32_t line = (uint32_t)(r >> 1);
        uint32_t off = line * 128 + ((((uint32_t)(r & 1) * 4 + (uint32_t)c) ^ (line & 7)) << 4);
        cp16(sdst + off, gp);
    }
}

// ===========================================================================
// gemm_proj: s = samples @ W^T + bias -> bf16 hi/lo.
// Block 128(M) x 128(N), warp tile 64x32 (8 warps = 2x4), KC=32, 3-stage ring.
// Whole-stage fragment buffering: both ks-groups' fragments loaded before any
// MMA -> group-1 crossbar traffic overlaps group-0 tensor execution.
// 1 CTA/SM (reg-heavy: ~96 frag + 64 acc regs).
// ===========================================================================
#define P_ALO 8192
#define P_BHI 16384
#define P_BLO 24576
#define P_STG 32768
#define P_SMEM (3 * P_STG)

__global__ __launch_bounds__(256, 1)
void gemm_proj(const __nv_bfloat16* __restrict__ Ahi, const __nv_bfloat16* __restrict__ Alo,
               const __nv_bfloat16* __restrict__ Bhi, const __nv_bfloat16* __restrict__ Blo,
               const float* __restrict__ bias,
               __nv_bfloat16* __restrict__ Chi, __nv_bfloat16* __restrict__ Clo)
{
    extern __shared__ __align__(1024) char smem[];
    const uint32_t sb = smem_u32(smem);
    const int tid = threadIdx.x;
    const size_t row0 = (size_t)blockIdx.y * 128;
    const size_t col0 = (size_t)blockIdx.x * 128;
    const int K = K3_;

    const int lane = tid & 31, warp = tid >> 5;
    const int wm = warp >> 2, wn = warp & 3;

    // lane math identical to gemm_sym (verified)
    const uint32_t dlA = (uint32_t)((lane & 15) >> 1);
    const uint32_t baseA = (uint32_t)(wm * 32 + dlA) * 128;
    uint32_t chA[2];
    #pragma unroll
    for (int ks = 0; ks < 2; ks++)
        chA[ks] = ((((uint32_t)(lane & 1) << 2) + (uint32_t)(2 * ks + (lane >> 4))) ^ dlA) << 4;
    const uint32_t vB  = (uint32_t)((lane & 7) | ((lane >> 4) << 3));
    const uint32_t dlB = vB >> 1;
    const uint32_t baseB = (uint32_t)(wn * 16 + dlB) * 128;
    uint32_t chB[2];
    #pragma unroll
    for (int ks = 0; ks < 2; ks++)
        chB[ks] = ((((uint32_t)(lane & 1) << 2) + (uint32_t)(2 * ks + ((lane >> 3) & 1))) ^ dlB) << 4;

    float acc[4][4][4];
    #pragma unroll
    for (int i = 0; i < 4; i++)
        #pragma unroll
        for (int j = 0; j < 4; j++)
            #pragma unroll
            for (int q = 0; q < 4; q++) acc[i][j][q] = 0.0f;

    const int NS = K / 32;     // 96
    {
        uint32_t s0 = sb, s1 = sb + P_STG;
        stage_rows<2>(s0 + 0,     Ahi, row0, K, 0, tid);
        stage_rows<2>(s0 + P_ALO, Alo, row0, K, 0, tid);
        stage_rows<2>(s0 + P_BHI, Bhi, col0, K, 0, tid);
        stage_rows<2>(s0 + P_BLO, Blo, col0, K, 0, tid);
        asm volatile("cp.async.commit_group;" ::: "memory");
        stage_rows<2>(s1 + 0,     Ahi, row0, K, 32, tid);
        stage_rows<2>(s1 + P_ALO, Alo, row0, K, 32, tid);
        stage_rows<2>(s1 + P_BHI, Bhi, col0, K, 32, tid);
        stage_rows<2>(s1 + P_BLO, Blo, col0, K, 32, tid);
        asm volatile("cp.async.commit_group;" ::: "memory");
    }

    int buf = 0;
    for (int st = 0; st < NS; st++) {
        if (st + 1 < NS) asm volatile("cp.async.wait_group 1;" ::: "memory");
        else             asm volatile("cp.async.wait_group 0;" ::: "memory");
        __syncthreads();

        const uint32_t sbuf = sb + (uint32_t)buf * P_STG;

        // ---- load ALL fragments for both ks-groups, then compute ----
        uint32_t ah[2][4][4], al[2][4][4], bh[2][4][2], bl[2][4][2];
        #pragma unroll
        for (int ks = 0; ks < 2; ks++) {
            #pragma unroll
            for (int am = 0; am < 4; am++) {
                ldsm4(sbuf + baseA + am * 1024 + chA[ks],
                      ah[ks][am][0], ah[ks][am][1], ah[ks][am][2], ah[ks][am][3]);
                ldsm4(sbuf + P_ALO + baseA + am * 1024 + chA[ks],
                      al[ks][am][0], al[ks][am][1], al[ks][am][2], al[ks][am][3]);
            }
            #pragma unroll
            for (int p = 0; p < 2; p++) {
                uint32_t r0, r1, r2, r3;
                ldsm4(sbuf + P_BHI + baseB + p * 1024 + chB[ks], r0, r1, r2, r3);
                bh[ks][2 * p][0] = r0; bh[ks][2 * p][1] = r1;
                bh[ks][2 * p + 1][0] = r2; bh[ks][2 * p + 1][1] = r3;
                ldsm4(sbuf + P_BLO + baseB + p * 1024 + chB[ks], r0, r1, r2, r3);
                bl[ks][2 * p][0] = r0; bl[ks][2 * p][1] = r1;
                bl[ks][2 * p + 1][0] = r2; bl[ks][2 * p + 1][1] = r3;
            }
        }
        #pragma unroll
        for (int ks = 0; ks < 2; ks++)
            #pragma unroll
            for (int am = 0; am < 4; am++)
                #pragma unroll
                for (int an = 0; an < 4; an++) {
                    mma16816(acc[am][an], ah[ks][am], bh[ks][an]);
                    mma16816(acc[am][an], ah[ks][am], bl[ks][an]);
                    mma16816(acc[am][an], al[ks][am], bh[ks][an]);
                }

        if (st + 2 < NS) {
            int nb = buf + 2; if (nb >= 3) nb -= 3;
            const uint32_t np = sb + (uint32_t)nb * P_STG;
            const int k0 = (st + 2) * 32;
            stage_rows<2>(np + 0,     Ahi, row0, K, k0, tid);
            stage_rows<2>(np + P_ALO, Alo, row0, K, k0, tid);
            stage_rows<2>(np + P_BHI, Bhi, col0, K, k0, tid);
            stage_rows<2>(np + P_BLO, Blo, col0, K, k0, tid);
            asm volatile("cp.async.commit_group;" ::: "memory");
        }
        if (++buf == 3) buf = 0;
    }

    const int re = (int)row0 + wm * 64 + (lane >> 2);
    const int ce = (int)col0 + wn * 32 + (lane & 3) * 2;
    #pragma unroll
    for (int am = 0; am < 4; am++) {
        #pragma unroll
        for (int an = 0; an < 4; an++) {
            const int r = re + am * 16;
            const int c = ce + an * 8;
            float v0 = acc[am][an][0] + bias[c];
            float v1 = acc[am][an][1] + bias[c + 1];
            float v2 = acc[am][an][2] + bias[c];
            float v3 = acc[am][an][3] + bias[c + 1];
            __nv_bfloat16 h0 = __float2bfloat16(v0), h1 = __float2bfloat16(v1);
            __nv_bfloat16 h2 = __float2bfloat16(v2), h3 = __float2bfloat16(v3);
            __nv_bfloat162 lp0 = __floats2bfloat162_rn(v0 - __bfloat162float(h0),
                                                       v1 - __bfloat162float(h1));
            __nv_bfloat162 lp1 = __floats2bfloat162_rn(v2 - __bfloat162float(h2),
                                                       v3 - __bfloat162float(h3));
            uint32_t hp0 = (uint32_t)__bfloat16_as_ushort(h0) |
                           ((uint32_t)__bfloat16_as_ushort(h1) << 16);
            uint32_t hp1 = (uint32_t)__bfloat16_as_ushort(h2) |
                           ((uint32_t)__bfloat16_as_ushort(h3) << 16);
            *(uint32_t*)&Chi[(size_t)r * H_ + c]       = hp0;
            *(uint32_t*)&Chi[(size_t)(r + 8) * H_ + c] = hp1;
            *(uint32_t*)&Clo[(size_t)r * H_ + c]       = *reinterpret_cast<uint32_t*>(&lp0);
            *(uint32_t*)&Clo[(size_t)(r + 8) * H_ + c] = *reinterpret_cast<uint32_t*>(&lp1);
        }
    }
}

// ===========================================================================
// gemm_sym: graph[b] = s[b] @ s[b]^T (fp32), upper-tri tiles + mirror write.
// Block 128x128, warp 64x32, KC=32, 3-stage ring, 2 CTAs/SM.  (unchanged R10)
// ===========================================================================
#define S_ALO 8192
#define S_BHI 16384
#define S_BLO 24576
#define S_STG 32768
#define S_SMEM (3 * S_STG)

__global__ __launch_bounds__(256, 2)
void gemm_sym(const __nv_bfloat16* __restrict__ sh, const __nv_bfloat16* __restrict__ sl,
              float* __restrict__ G)
{
    extern __shared__ __align__(1024) char smem[];
    const uint32_t sb = smem_u32(smem);
    const int tid = threadIdx.x;
    const int bz  = blockIdx.z;
    const int K = H_;

    int by = 0, rem = blockIdx.x;
    #pragma unroll
    for (int i = 0; i < 8; i++) {
        if (rem >= 8 - by) { rem -= (8 - by); by++; }
    }
    const int bx = by + rem;

    const __nv_bfloat16* Ahi = sh + (size_t)bz * L_ * H_;
    const __nv_bfloat16* Alo = sl + (size_t)bz * L_ * H_;
    float* Gb = G + (size_t)bz * L_ * L_;

    const size_t row0 = (size_t)by * 128;
    const size_t col0 = (size_t)bx * 128;

    const int lane = tid & 31, warp = tid >> 5;
    const int wm = warp >> 2, wn = warp & 3;

    const uint32_t dlA = (uint32_t)((lane & 15) >> 1);
    const uint32_t baseA = (uint32_t)(wm * 32 + dlA) * 128;
    uint32_t chA[2];
    #pragma unroll
    for (int ks = 0; ks < 2; ks++)
        chA[ks] = ((((uint32_t)(lane & 1) << 2) + (uint32_t)(2 * ks + (lane >> 4))) ^ dlA) << 4;
    const uint32_t vB  = (uint32_t)((lane & 7) | ((lane >> 4) << 3));
    const uint32_t dlB = vB >> 1;
    const uint32_t baseB = (uint32_t)(wn * 16 + dlB) * 128;
    uint32_t chB[2];
    #pragma unroll
    for (int ks = 0; ks < 2; ks++)
        chB[ks] = ((((uint32_t)(lane & 1) << 2) + (uint32_t)(2 * ks + ((lane >> 3) & 1))) ^ dlB) << 4;

    float acc[4][4][4];
    #pragma unroll
    for (int i = 0; i < 4; i++)
        #pragma unroll
        for (int j = 0; j < 4; j++)
            #pragma unroll
            for (int q = 0; q < 4; q++) acc[i][j][q] = 0.0f;

    const int NS = K / 32;
    {
        uint32_t s0 = sb, s1 = sb + S_STG;
        stage_rows<2>(s0 + 0,     Ahi, row0, K, 0, tid);
        stage_rows<2>(s0 + S_ALO, Alo, row0, K, 0, tid);
        stage_rows<2>(s0 + S_BHI, Ahi, col0, K, 0, tid);
        stage_rows<2>(s0 + S_BLO, Alo, col0, K, 0, tid);
        asm volatile("cp.async.commit_group;" ::: "memory");
        stage_rows<2>(s1 + 0,     Ahi, row0, K, 32, tid);
        stage_rows<2>(s1 + S_ALO, Alo, row0, K, 32, tid);
        stage_rows<2>(s1 + S_BHI, Ahi, col0, K, 32, tid);
        stage_rows<2>(s1 + S_BLO, Alo, col0, K, 32, tid);
        asm volatile("cp.async.commit_group;" ::: "memory");
    }

    int buf = 0;
    for (int st = 0; st < NS; st++) {
        if (st + 1 < NS) asm volatile("cp.async.wait_group 1;" ::: "memory");
        else             asm volatile("cp.async.wait_group 0;" ::: "memory");
        __syncthreads();

        const uint32_t sbuf = sb + (uint32_t)buf * S_STG;
        #pragma unroll
        for (int ks = 0; ks < 2; ks++) {
            uint32_t ah[4][4], al[4][4];
            #pragma unroll
            for (int am = 0; am < 4; am++) {
                ldsm4(sbuf + baseA + am * 1024 + chA[ks],
                      ah[am][0], ah[am][1], ah[am][2], ah[am][3]);
                ldsm4(sbuf + S_ALO + baseA + am * 1024 + chA[ks],
                      al[am][0], al[am][1], al[am][2], al[am][3]);
            }
            uint32_t bh[4][2], bl[4][2];
            #pragma unroll
            for (int p = 0; p < 2; p++) {
                uint32_t r0, r1, r2, r3;
                ldsm4(sbuf + S_BHI + baseB + p * 1024 + chB[ks], r0, r1, r2, r3);
                bh[2 * p][0] = r0; bh[2 * p][1] = r1;
                bh[2 * p + 1][0] = r2; bh[2 * p + 1][1] = r3;
                ldsm4(sbuf + S_BLO + baseB + p * 1024 + chB[ks], r0, r1, r2, r3);
                bl[2 * p][0] = r0; bl[2 * p][1] = r1;
                bl[2 * p + 1][0] = r2; bl[2 * p + 1][1] = r3;
            }
            #pragma unroll
            for (int am = 0; am < 4; am++)
                #pragma unroll
                for (int an = 0; an < 4; an++) {
                    mma16816(acc[am][an], ah[am], bh[an]);
                    mma16816(acc[am][an], ah[am], bl[an]);
                    mma16816(acc[am][an], al[am], bh[an]);
                }
        }

        if (st + 2 < NS) {
            int nb = buf + 2; if (nb >= 3) nb -= 3;
            const uint32_t np = sb + (uint32_t)nb * S_STG;
            const int k0 = (st + 2) * 32;
            stage_rows<2>(np + 0,     Ahi, row0, K, k0, tid);
            stage_rows<2>(np + S_ALO, Alo, row0, K, k0, tid);
            stage_rows<2>(np + S_BHI, Ahi, col0, K, k0, tid);
            stage_rows<2>(np + S_BLO, Alo, col0, K, k0, tid);
            asm volatile("cp.async.commit_group;" ::: "memory");
        }
        if (++buf == 3) buf = 0;
    }

    // all warps must finish reading the smem ring before it is reused below
    __syncthreads();

    const int rl = wm * 64 + (lane >> 2);
    const int cl = wn * 32 + (lane & 3) * 2;
    float* eb = (float*)smem;     // 128 x 129 fp32 staging
    #pragma unroll
    for (int am = 0; am < 4; am++) {
        #pragma unroll
        for (int an = 0; an < 4; an++) {
            const int r = rl + am * 16;
            const int c = cl + an * 8;
            float v0 = acc[am][an][0], v1 = acc[am][an][1];
            float v2 = acc[am][an][2], v3 = acc[am][an][3];
            *(float2*)&Gb[(row0 + r) * L_ + col0 + c]     = make_float2(v0, v1);
            *(float2*)&Gb[(row0 + r + 8) * L_ + col0 + c] = make_float2(v2, v3);
            if (bx != by) {
                eb[r * 129 + c] = v0;       eb[r * 129 + c + 1] = v1;
                eb[(r + 8) * 129 + c] = v2; eb[(r + 8) * 129 + c + 1] = v3;
            }
        }
    }
    if (bx != by) {
        __syncthreads();
        #pragma unroll 4
        for (int it = 0; it < 64; it++) {
            int idx = tid + it * 256;
            int j = idx >> 7, i = idx & 127;
            Gb[(col0 + j) * L_ + row0 + i] = eb[i * 129 + j];
        }
    }
}

// ---------------------------------------------------------------------------
// Row softmax, diag masked; emits A as bf16 hi/lo.
// ---------------------------------------------------------------------------
__global__ __launch_bounds__(256)
void softmax_kernel(const float* __restrict__ G, __nv_bfloat16* __restrict__ Ah,
                    __nv_bfloat16* __restrict__ Al)
{
    const int l = blockIdx.x;
    const int b = blockIdx.y;
    const size_t rowoff = ((size_t)b * L_ + (size_t)l) * L_;
    const int tid = threadIdx.x;

    float4 v = ((const float4*)(G + rowoff))[tid];
    if ((l >> 2) == tid) (&v.x)[l & 3] -= 1e5f;

    float mx = fmaxf(fmaxf(v.x, v.y), fmaxf(v.z, v.w));

    __shared__ float red1[8];
    __shared__ float red2[8];
    #pragma unroll
    for (int o = 16; o > 0; o >>= 1)
        mx = fmaxf(mx, __shfl_xor_sync(0xffffffffu, mx, o));
    if ((tid & 31) == 0) red1[tid >> 5] = mx;
    __syncthreads();
    mx = red1[0];
    #pragma unroll
    for (int i = 1; i < 8; i++) mx = fmaxf(mx, red1[i]);

    v.x = __expf(v.x - mx); v.y = __expf(v.y - mx);
    v.z = __expf(v.z - mx); v.w = __expf(v.w - mx);
    float s = (v.x + v.y) + (v.z + v.w);
    #pragma unroll
    for (int o = 16; o > 0; o >>= 1)
        s += __shfl_xor_sync(0xffffffffu, s, o);
    if ((tid & 31) == 0) red2[tid >> 5] = s;
    __syncthreads();
    s = red2[0];
    #pragma unroll
    for (int i = 1; i < 8; i++) s += red2[i];

    const float inv = 1.0f / s;
    v.x *= inv; v.y *= inv; v.z *= inv; v.w *= inv;

    __nv_bfloat16 h0 = __float2bfloat16(v.x), h1 = __float2bfloat16(v.y);
    __nv_bfloat16 h2 = __float2bfloat16(v.z), h3 = __float2bfloat16(v.w);
    float l0 = v.x - __bfloat162float(h0);
    float l1 = v.y - __bfloat162float(h1);
    float l2 = v.z - __bfloat162float(h2);
    float l3 = v.w - __bfloat162float(h3);
    uint2 hv, lv;
    hv.x = (uint32_t)__bfloat16_as_ushort(h0) | ((uint32_t)__bfloat16_as_ushort(h1) << 16);
    hv.y = (uint32_t)__bfloat16_as_ushort(h2) | ((uint32_t)__bfloat16_as_ushort(h3) << 16);
    __nv_bfloat162 p01 = __floats2bfloat162_rn(l0, l1);
    __nv_bfloat162 p23 = __floats2bfloat162_rn(l2, l3);
    lv.x = *reinterpret_cast<uint32_t*>(&p01);
    lv.y = *reinterpret_cast<uint32_t*>(&p23);
    ((uint2*)(Ah + rowoff))[tid] = hv;
    ((uint2*)(Al + rowoff))[tid] = lv;
}

// ---------------------------------------------------------------------------
// B0 = (sup - colsum/total) * row_has (fp32);  u1 = B0 as bf16 hi/lo.
// ---------------------------------------------------------------------------
__global__ __launch_bounds__(1024)
void b0_kernel(const float* __restrict__ lab, float* __restrict__ B0,
               __nv_bfloat16* __restrict__ uh, __nv_bfloat16* __restrict__ ul)
{
    const int b = blockIdx.x;
    const int t = threadIdx.x;
    const float* supb = lab + (size_t)b * L_ * N_;

    __shared__ float colp[16][64];
    __shared__ float s_col[64];
    __shared__ float s_rh[L_];
    __shared__ float s_tot;

    if (t == 0) s_tot = 0.0f;

    {
        const int c = t & 63, g = t >> 6;
        float cp = 0.0f;
        #pragma unroll 4
        for (int i = 0; i < 64; i++)
            cp += supb[(size_t)(i * 16 + g) * N_ + c];
        colp[g][c] = cp;
    }
    {
        const int w = t >> 5, lane = t & 31;
        for (int r = w; r < L_; r += 32) {
            float v = supb[(size_t)r * N_ + lane] + supb[(size_t)r * N_ + 32 + lane];
            #pragma unroll
            for (int o = 16; o > 0; o >>= 1) v += __shfl_xor_sync(0xffffffffu, v, o);
            if (lane == 0) s_rh[r] = (v > 0.5f) ? 1.0f : 0.0f;
        }
    }
    __syncthreads();
    if (t < 64) {
        float s = 0.0f;
        #pragma unroll
        for (int j = 0; j < 16; j++) s += colp[j][t];
        s_col[t] = s;
    }
    {
        float v = s_rh[t];
        #pragma unroll
        for (int o = 16; o > 0; o >>= 1) v += __shfl_xor_sync(0xffffffffu, v, o);
        if ((t & 31) == 0) atomicAdd(&s_tot, v);
    }
    __syncthreads();

    const float inv = 1.0f / s_tot;
    const size_t boff = (size_t)b * L_ * N_;
    #pragma unroll 4
    for (int i = 0; i < 64; i++) {
        const int idx = t + i * 1024;
        const int r = idx >> 6, n = idx & 63;
        float v = (supb[idx] - s_col[n] * inv) * s_rh[r];
        B0[boff + idx] = v;
        __nv_bfloat16 h = __float2bfloat16(v);
        uh[boff + idx] = h;
        ul[boff + idx] = __float2bfloat16(v - __bfloat162float(h));
    }
}

// ---------------------------------------------------------------------------
// Tensor-core power-iteration step (3-stage ring, known-good R10 version).
// ---------------------------------------------------------------------------
#define IT_KC   32
#define IT_AL_OFF 8192
#define IT_UH_OFF 16384
#define IT_UL_OFF 20480
#define IT_STG  24576
#define IT_SMEM (3 * IT_STG)

__device__ __forceinline__ void it_stage(uint32_t sbuf,
        const __nv_bfloat16* __restrict__ Ah, const __nv_bfloat16* __restrict__ Al,
        const __nv_bfloat16* __restrict__ uh, const __nv_bfloat16* __restrict__ ul,
        int l0, int k0, int tid)
{
    #pragma unroll
    for (int i = 0; i < 2; i++) {
        int idx = tid + i * 256;
        int r = idx >> 4, c = idx & 15;
        uint32_t off = (uint32_t)r * 256 + ((uint32_t)(c ^ (r & 15)) << 4);
        const void* gp = Ah + (size_t)(k0 + r) * L_ + l0 + c * 8;
        cp16(sbuf + off, gp);
        const void* gq = Al + (size_t)(k0 + r) * L_ + l0 + c * 8;
        cp16(sbuf + IT_AL_OFF + off, gq);
    }
    {
        int r = tid >> 3, c = tid & 7;
        uint32_t off = (uint32_t)r * 128 + ((uint32_t)(c ^ (r & 7)) << 4);
        cp16(sbuf + IT_UH_OFF + off, uh + (size_t)(k0 + r) * N_ + c * 8);
        cp16(sbuf + IT_UL_OFF + off, ul + (size_t)(k0 + r) * N_ + c * 8);
    }
    asm volatile("cp.async.commit_group;" ::: "memory");
}

template<int LAST>
__global__ __launch_bounds__(256, 2)
void iter_mma(const __nv_bfloat16* __restrict__ Ah, const __nv_bfloat16* __restrict__ Al,
              const __nv_bfloat16* __restrict__ uh_in, const __nv_bfloat16* __restrict__ ul_in,
              const float* __restrict__ B0, const float* __restrict__ pred,
              __nv_bfloat16* __restrict__ uh_out, __nv_bfloat16* __restrict__ ul_out,
              float* __restrict__ f32out)
{
    extern __shared__ __align__(1024) char smem[];
    const uint32_t sb = smem_u32(smem);
    const int tid = threadIdx.x;
    const int b = blockIdx.z;
    const int l0 = blockIdx.x * 128;

    const __nv_bfloat16* Ahb = Ah + (size_t)b * L_ * L_;
    const __nv_bfloat16* Alb = Al + (size_t)b * L_ * L_;
    const __nv_bfloat16* uhb = uh_in + (size_t)b * L_ * N_;
    const __nv_bfloat16* ulb = ul_in + (size_t)b * L_ * N_;

    const int lane = tid & 31, warp = tid >> 5;
    const int wm = warp >> 2, wn = warp & 3;

    uint32_t aoff[2][4];
    {
        uint32_t k_lane = (uint32_t)((lane & 7) + ((lane >> 4) << 3));
        uint32_t mbit = (uint32_t)((lane >> 3) & 1);
        #pragma unroll
        for (int ks = 0; ks < 2; ks++) {
            uint32_t k = (uint32_t)(ks * 16) + k_lane;
            #pragma unroll
            for (int am = 0; am < 4; am++) {
                uint32_t cA = (uint32_t)(wm * 8 + am * 2) + mbit;
                aoff[ks][am] = k * 256 + ((cA ^ (k & 15)) << 4);
            }
        }
    }
    uint32_t uoff[2];
    {
        uint32_t k_lane = (uint32_t)((lane & 7) + (((lane >> 3) & 1) << 3));
        uint32_t cn = (uint32_t)(wn * 2 + (lane >> 4));
        #pragma unroll
        for (int ks = 0; ks < 2; ks++) {
            uint32_t k = (uint32_t)(ks * 16) + k_lane;
            uoff[ks] = k * 128 + ((cn ^ (k & 7)) << 4);
        }
    }

    float acc[4][2][4];
    #pragma unroll
    for (int i = 0; i < 4; i++)
        #pragma unroll
        for (int j = 0; j < 2; j++)
            #pragma unroll
            for (int q = 0; q < 4; q++) acc[i][j][q] = 0.0f;

    const int NS = L_ / IT_KC;
    it_stage(sb + 0 * IT_STG, Ahb, Alb, uhb, ulb, l0, 0,      tid);
    it_stage(sb + 1 * IT_STG, Ahb, Alb, uhb, ulb, l0, IT_KC,  tid);

    int buf = 0;
    for (int st = 0; st < NS; st++) {
        if (st + 1 < NS) asm volatile("cp.async.wait_group 1;" ::: "memory");
        else             asm volatile("cp.async.wait_group 0;" ::: "memory");
        __syncthreads();

        const uint32_t sbuf = sb + (uint32_t)buf * IT_STG;
        #pragma unroll
        for (int ks = 0; ks < 2; ks++) {
            uint32_t ah[4][4], al4[4][4];
            #pragma unroll
            for (int am = 0; am < 4; am++) {
                ldsm4t(sbuf + aoff[ks][am],
                       ah[am][0], ah[am][1], ah[am][2], ah[am][3]);
                ldsm4t(sbuf + IT_AL_OFF + aoff[ks][am],
                       al4[am][0], al4[am][1], al4[am][2], al4[am][3]);
            }
            uint32_t bh[2][2], bl[2][2];
            {
                uint32_t r0, r1, r2, r3;
                ldsm4t(sbuf + IT_UH_OFF + uoff[ks], r0, r1, r2, r3);
                bh[0][0] = r0; bh[0][1] = r1; bh[1][0] = r2; bh[1][1] = r3;
                ldsm4t(sbuf + IT_UL_OFF + uoff[ks], r0, r1, r2, r3);
                bl[0][0] = r0; bl[0][1] = r1; bl[1][0] = r2; bl[1][1] = r3;
            }
            #pragma unroll
            for (int am = 0; am < 4; am++)
                #pragma unroll
                for (int an = 0; an < 2; an++) {
                    mma16816(acc[am][an], ah[am], bh[an]);
                    mma16816(acc[am][an], ah[am], bl[an]);
                    mma16816(acc[am][an], al4[am], bh[an]);
                }
        }

        if (st + 2 < NS) {
            int nb = buf + 2; if (nb >= 3) nb -= 3;
            it_stage(sb + (uint32_t)nb * IT_STG, Ahb, Alb, uhb, ulb,
                     l0, (st + 2) * IT_KC, tid);
        }
        if (++buf == 3) buf = 0;
    }

    const int lbase = l0 + wm * 64 + (lane >> 2);
    const int nbase = wn * 16 + (lane & 3) * 2;
    #pragma unroll
    for (int am = 0; am < 4; am++) {
        #pragma unroll
        for (int an = 0; an < 2; an++) {
            const int l = lbase + am * 16;
            const int n = nbase + an * 8;
            const size_t o0 = ((size_t)b * L_ + l) * N_ + n;
            const size_t o1 = o0 + 8 * N_;
            float v0 = acc[am][an][0] + B0[o0];
            float v1 = acc[am][an][1] + B0[o0 + 1];
            float v2 = acc[am][an][2] + B0[o1];
            float v3 = acc[am][an][3] + B0[o1 + 1];
            if (pred) {
                v0 += pred[o0]; v1 += pred[o0 + 1];
                v2 += pred[o1]; v3 += pred[o1 + 1];
            }
            if (LAST) {
                *(float2*)&f32out[o0] = make_float2(v0, v1);
                *(float2*)&f32out[o1] = make_float2(v2, v3);
            } else {
                __nv_bfloat16 h0 = __float2bfloat16(v0), h1 = __float2bfloat16(v1);
                __nv_bfloat16 h2 = __float2bfloat16(v2), h3 = __float2bfloat16(v3);
                __nv_bfloat162 lo01 = __floats2bfloat162_rn(v0 - __bfloat162float(h0),
                                                            v1 - __bfloat162float(h1));
                __nv_bfloat162 lo23 = __floats2bfloat162_rn(v2 - __bfloat162float(h2),
                                                            v3 - __bfloat162float(h3));
                uint32_t hp0 = (uint32_t)__bfloat16_as_ushort(h0) |
                               ((uint32_t)__bfloat16_as_ushort(h1) << 16);
                uint32_t hp1 = (uint32_t)__bfloat16_as_ushort(h2) |
                               ((uint32_t)__bfloat16_as_ushort(h3) << 16);
                *(uint32_t*)&uh_out[o0] = hp0;
                *(uint32_t*)&uh_out[o1] = hp1;
                *(uint32_t*)&ul_out[o0] = *reinterpret_cast<uint32_t*>(&lo01);
                *(uint32_t*)&ul_out[o1] = *reinterpret_cast<uint32_t*>(&lo23);
            }
        }
    }
}

// ---------------------------------------------------------------------------
extern "C" void kernel_launch(void* const* d_in, const int* in_sizes, int n_in,
                              void* d_out, int out_size)
{
    const float* samples = (const float*)d_in[0];  // [8,1024,3072]
    const float* label   = (const float*)d_in[1];  // [8,1024,64]
    const float* predict = (const float*)d_in[2];  // [8,1024,64]
    const float* W       = (const float*)d_in[3];  // [1024,3072]
    const float* bproj   = (const float*)d_in[4];  // [1024]
    float* out = (float*)d_out;                    // [8,1024,64]

    __nv_bfloat16 *smph, *smpl, *Wh, *Wl, *sh, *sl, *uh1, *ul1, *uh2, *ul2;
    float *A, *B0;
    cudaGetSymbolAddress((void**)&smph, g_smp_hi);
    cudaGetSymbolAddress((void**)&smpl, g_smp_lo);
    cudaGetSymbolAddress((void**)&Wh,   g_W_hi);
    cudaGetSymbolAddress((void**)&Wl,   g_W_lo);
    cudaGetSymbolAddress((void**)&sh,   g_s_hi);
    cudaGetSymbolAddress((void**)&sl,   g_s_lo);
    cudaGetSymbolAddress((void**)&A,    g_A);
    cudaGetSymbolAddress((void**)&B0,   g_B0);
    cudaGetSymbolAddress((void**)&uh1,  g_uh1);
    cudaGetSymbolAddress((void**)&ul1,  g_ul1);
    cudaGetSymbolAddress((void**)&uh2,  g_uh2);
    cudaGetSymbolAddress((void**)&ul2,  g_ul2);

    cudaFuncSetAttribute(gemm_proj, cudaFuncAttributeMaxDynamicSharedMemorySize, P_SMEM);
    cudaFuncSetAttribute(gemm_sym,  cudaFuncAttributeMaxDynamicSharedMemorySize, S_SMEM);
    cudaFuncSetAttribute(iter_mma<0>, cudaFuncAttributeMaxDynamicSharedMemorySize, IT_SMEM);
    cudaFuncSetAttribute(iter_mma<1>, cudaFuncAttributeMaxDynamicSharedMemorySize, IT_SMEM);

    {
        int n4 = (B_ * L_ * K3_) / 4;
        split_kernel<<<(n4 + 255) / 256, 256>>>(samples, smph, smpl, n4);
        int w4 = (H_ * K3_) / 4;
        split_kernel<<<(w4 + 255) / 256, 256>>>(W, Wh, Wl, w4);
    }

    gemm_proj<<<dim3(H_ / 128, (B_ * L_) / 128, 1), 256, P_SMEM>>>(
        smph, smpl, Wh, Wl, bproj, sh, sl);

    gemm_sym<<<dim3(36, 1, B_), 256, S_SMEM>>>(sh, sl, A);

    softmax_kernel<<<dim3(L_, B_), 256>>>(A, sh, sl);

    b0_kernel<<<B_, 1024>>>(label, B0, uh1, ul1);

    dim3 ig(L_ / 128, 1, B_);
    iter_mma<0><<<ig, 256, IT_SMEM>>>(sh, sl, uh1, ul1, B0, nullptr,  uh2, ul2, nullptr); // t=2
    iter_mma<0><<<ig, 256, IT_SMEM>>>(sh, sl, uh2, ul2, B0, predict,  uh1, ul1, nullptr); // t=3
    iter_mma<0><<<ig, 256, IT_SMEM>>>(sh, sl, uh1, ul1, B0, nullptr,  uh2, ul2, nullptr); // t=4
    iter_mma<0><<<ig, 256, IT_SMEM>>>(sh, sl, uh2, ul2, B0, nullptr,  uh1, ul1, nullptr); // t=5
    iter_mma<1><<<ig, 256, IT_SMEM>>>(sh, sl, uh1, ul1, B0, nullptr,  nullptr, nullptr, out); // t=6
}

// round 13
// speedup vs baseline: 1.0618x; 1.0407x over previous
#include <cuda_runtime.h>
#include <cuda_bf16.h>
#include <cstddef>
#include <cstdint>

#define B_  8
#define L_  1024
#define H_  1024
#define K3_ 3072
#define N_  64

// ---------------------------------------------------------------------------
// Static scratch (no allocations allowed)
// ---------------------------------------------------------------------------
__device__ __align__(256) __nv_bfloat16 g_smp_hi[(size_t)B_ * L_ * K3_];
__device__ __align__(256) __nv_bfloat16 g_smp_lo[(size_t)B_ * L_ * K3_];
__device__ __align__(256) __nv_bfloat16 g_W_hi [(size_t)H_ * K3_];
__device__ __align__(256) __nv_bfloat16 g_W_lo [(size_t)H_ * K3_];
__device__ __align__(256) __nv_bfloat16 g_s_hi [(size_t)B_ * L_ * H_];  // later: A_hi
__device__ __align__(256) __nv_bfloat16 g_s_lo [(size_t)B_ * L_ * H_];  // later: A_lo
__device__ __align__(256) float g_A [(size_t)B_ * L_ * L_];             // graph (fp32)
__device__ __align__(256) float g_B0[(size_t)B_ * L_ * N_];
__device__ __align__(256) __nv_bfloat16 g_uh1[(size_t)B_ * L_ * N_];
__device__ __align__(256) __nv_bfloat16 g_ul1[(size_t)B_ * L_ * N_];
__device__ __align__(256) __nv_bfloat16 g_uh2[(size_t)B_ * L_ * N_];
__device__ __align__(256) __nv_bfloat16 g_ul2[(size_t)B_ * L_ * N_];

// ---------------------------------------------------------------------------
// PTX helpers (baseline-PTX only: cp.async / ldmatrix / mma.sync)
// ---------------------------------------------------------------------------
__device__ __forceinline__ uint32_t smem_u32(const void* p) {
    uint32_t a;
    asm("{ .reg .u64 t; cvta.to.shared.u64 t, %1; cvt.u32.u64 %0, t; }" : "=r"(a) : "l"(p));
    return a;
}

__device__ __forceinline__ void cp16(uint32_t saddr, const void* g) {
    asm volatile("cp.async.cg.shared.global [%0], [%1], 16;" :: "r"(saddr), "l"(g) : "memory");
}

__device__ __forceinline__ void ldsm4(uint32_t addr, uint32_t& r0, uint32_t& r1,
                                      uint32_t& r2, uint32_t& r3) {
    asm volatile("ldmatrix.sync.aligned.m8n8.x4.shared.b16 {%0,%1,%2,%3}, [%4];"
                 : "=r"(r0), "=r"(r1), "=r"(r2), "=r"(r3) : "r"(addr));
}

__device__ __forceinline__ void ldsm4t(uint32_t addr, uint32_t& r0, uint32_t& r1,
                                       uint32_t& r2, uint32_t& r3) {
    asm volatile("ldmatrix.sync.aligned.m8n8.x4.trans.shared.b16 {%0,%1,%2,%3}, [%4];"
                 : "=r"(r0), "=r"(r1), "=r"(r2), "=r"(r3) : "r"(addr));
}

__device__ __forceinline__ void mma16816(float* c, const uint32_t* a, const uint32_t* b) {
    asm volatile(
        "mma.sync.aligned.m16n8k16.row.col.f32.bf16.bf16.f32 "
        "{%0,%1,%2,%3}, {%4,%5,%6,%7}, {%8,%9}, {%0,%1,%2,%3};"
        : "+f"(c[0]), "+f"(c[1]), "+f"(c[2]), "+f"(c[3])
        : "r"(a[0]), "r"(a[1]), "r"(a[2]), "r"(a[3]), "r"(b[0]), "r"(b[1]));
}

// ---------------------------------------------------------------------------
// fp32 -> bf16 hi/lo split
// ---------------------------------------------------------------------------
__global__ __launch_bounds__(256)
void split_kernel(const float* __restrict__ x, __nv_bfloat16* __restrict__ hi,
                  __nv_bfloat16* __restrict__ lo, int n4)
{
    int i = blockIdx.x * blockDim.x + threadIdx.x;
    if (i >= n4) return;
    float4 v = ((const float4*)x)[i];
    __nv_bfloat16 h0 = __float2bfloat16(v.x), h1 = __float2bfloat16(v.y);
    __nv_bfloat16 h2 = __float2bfloat16(v.z), h3 = __float2bfloat16(v.w);
    float r0 = v.x - __bfloat162float(h0);
    float r1 = v.y - __bfloat162float(h1);
    float r2 = v.z - __bfloat162float(h2);
    float r3 = v.w - __bfloat162float(h3);
    uint2 hv, lv;
    hv.x = (uint32_t)__bfloat16_as_ushort(h0) | ((uint32_t)__bfloat16_as_ushort(h1) << 16);
    hv.y = (uint32_t)__bfloat16_as_ushort(h2) | ((uint32_t)__bfloat16_as_ushort(h3) << 16);
    __nv_bfloat162 l01 = __floats2bfloat162_rn(r0, r1);
    __nv_bfloat162 l23 = __floats2bfloat162_rn(r2, r3);
    lv.x = *reinterpret_cast<uint32_t*>(&l01);
    lv.y = *reinterpret_cast<uint32_t*>(&l23);
    ((uint2*)hi)[i] = hv;
    ((uint2*)lo)[i] = lv;
}

// ---------------------------------------------------------------------------
// Shared staging helper: (ITERS*64) rows x 32k bf16 tile, paired-row swizzle
// ---------------------------------------------------------------------------
template<int ITERS>
__device__ __forceinline__ void stage_rows(uint32_t sdst, const __nv_bfloat16* __restrict__ g,
                                           size_t row0, int ldk, int k0, int tid)
{
    #pragma unroll
    for (int i = 0; i < ITERS; i++) {
        int idx = tid + i * 256;
        int r = idx >> 2, c = idx & 3;
        const void* gp = g + (row0 + (size_t)r) * (size_t)ldk + k0 + c * 8;
        uint32_t line = (uint32_t)(r >> 1);
        uint32_t off = line * 128 + ((((uint32_t)(r & 1) * 4 + (uint32_t)c) ^ (line & 7)) << 4);
        cp16(sdst + off, gp);
    }
}

// ===========================================================================
// gemm_proj: s = samples @ W^T + bias -> bf16 hi/lo.   (R10 structure; MMA
// loops reordered product-major so consecutive MMAs hit distinct accumulators)
// Block 128(M) x 256(N), warp tile 64x64 (8 warps = 2x4), KC=32, 3-stage ring.
// ===========================================================================
#define P_ALO 8192
#define P_BHI 16384
#define P_BLO 32768
#define P_STG 49152
#define P_SMEM (3 * P_STG)

__global__ __launch_bounds__(256, 1)
void gemm_proj(const __nv_bfloat16* __restrict__ Ahi, const __nv_bfloat16* __restrict__ Alo,
               const __nv_bfloat16* __restrict__ Bhi, const __nv_bfloat16* __restrict__ Blo,
               const float* __restrict__ bias,
               __nv_bfloat16* __restrict__ Chi, __nv_bfloat16* __restrict__ Clo)
{
    extern __shared__ __align__(1024) char smem[];
    const uint32_t sb = smem_u32(smem);
    const int tid = threadIdx.x;
    const size_t row0 = (size_t)blockIdx.y * 128;
    const size_t col0 = (size_t)blockIdx.x * 256;
    const int K = K3_;

    const int lane = tid & 31, warp = tid >> 5;
    const int wm = warp >> 2, wn = warp & 3;

    const uint32_t dlA = (uint32_t)((lane & 15) >> 1);
    const uint32_t baseA = (uint32_t)(wm * 32 + dlA) * 128;
    uint32_t chA[2];
    #pragma unroll
    for (int ks = 0; ks < 2; ks++)
        chA[ks] = ((((uint32_t)(lane & 1) << 2) + (uint32_t)(2 * ks + (lane >> 4))) ^ dlA) << 4;
    const uint32_t vB  = (uint32_t)((lane & 7) | ((lane >> 4) << 3));
    const uint32_t dlB = vB >> 1;
    const uint32_t baseB = (uint32_t)(wn * 32 + dlB) * 128;
    uint32_t chB[2];
    #pragma unroll
    for (int ks = 0; ks < 2; ks++)
        chB[ks] = ((((uint32_t)(lane & 1) << 2) + (uint32_t)(2 * ks + ((lane >> 3) & 1))) ^ dlB) << 4;

    float acc[4][8][4];
    #pragma unroll
    for (int i = 0; i < 4; i++)
        #pragma unroll
        for (int j = 0; j < 8; j++)
            #pragma unroll
            for (int q = 0; q < 4; q++) acc[i][j][q] = 0.0f;

    const int NS = K / 32;
    {
        uint32_t s0 = sb, s1 = sb + P_STG;
        stage_rows<2>(s0 + 0,     Ahi, row0, K, 0, tid);
        stage_rows<2>(s0 + P_ALO, Alo, row0, K, 0, tid);
        stage_rows<4>(s0 + P_BHI, Bhi, col0, K, 0, tid);
        stage_rows<4>(s0 + P_BLO, Blo, col0, K, 0, tid);
        asm volatile("cp.async.commit_group;" ::: "memory");
        stage_rows<2>(s1 + 0,     Ahi, row0, K, 32, tid);
        stage_rows<2>(s1 + P_ALO, Alo, row0, K, 32, tid);
        stage_rows<4>(s1 + P_BHI, Bhi, col0, K, 32, tid);
        stage_rows<4>(s1 + P_BLO, Blo, col0, K, 32, tid);
        asm volatile("cp.async.commit_group;" ::: "memory");
    }

    int buf = 0;
    for (int st = 0; st < NS; st++) {
        if (st + 1 < NS) asm volatile("cp.async.wait_group 1;" ::: "memory");
        else             asm volatile("cp.async.wait_group 0;" ::: "memory");
        __syncthreads();

        const uint32_t sbuf = sb + (uint32_t)buf * P_STG;
        #pragma unroll
        for (int ks = 0; ks < 2; ks++) {
            uint32_t ah[4][4], al[4][4];
            #pragma unroll
            for (int am = 0; am < 4; am++) {
                ldsm4(sbuf + baseA + am * 1024 + chA[ks],
                      ah[am][0], ah[am][1], ah[am][2], ah[am][3]);
                ldsm4(sbuf + P_ALO + baseA + am * 1024 + chA[ks],
                      al[am][0], al[am][1], al[am][2], al[am][3]);
            }
            uint32_t bh[8][2], bl[8][2];
            #pragma unroll
            for (int p = 0; p < 4; p++) {
                uint32_t r0, r1, r2, r3;
                ldsm4(sbuf + P_BHI + baseB + p * 1024 + chB[ks], r0, r1, r2, r3);
                bh[2 * p][0] = r0; bh[2 * p][1] = r1;
                bh[2 * p + 1][0] = r2; bh[2 * p + 1][1] = r3;
                ldsm4(sbuf + P_BLO + baseB + p * 1024 + chB[ks], r0, r1, r2, r3);
                bl[2 * p][0] = r0; bl[2 * p][1] = r1;
                bl[2 * p + 1][0] = r2; bl[2 * p + 1][1] = r3;
            }
            // product-major: consecutive MMAs target distinct accumulators
            #pragma unroll
            for (int am = 0; am < 4; am++)
                #pragma unroll
                for (int an = 0; an < 8; an++)
                    mma16816(acc[am][an], ah[am], bh[an]);
            #pragma unroll
            for (int am = 0; am < 4; am++)
                #pragma unroll
                for (int an = 0; an < 8; an++)
                    mma16816(acc[am][an], ah[am], bl[an]);
            #pragma unroll
            for (int am = 0; am < 4; am++)
                #pragma unroll
                for (int an = 0; an < 8; an++)
                    mma16816(acc[am][an], al[am], bh[an]);
        }

        if (st + 2 < NS) {
            int nb = buf + 2; if (nb >= 3) nb -= 3;
            const uint32_t np = sb + (uint32_t)nb * P_STG;
            const int k0 = (st + 2) * 32;
            stage_rows<2>(np + 0,     Ahi, row0, K, k0, tid);
            stage_rows<2>(np + P_ALO, Alo, row0, K, k0, tid);
            stage_rows<4>(np + P_BHI, Bhi, col0, K, k0, tid);
            stage_rows<4>(np + P_BLO, Blo, col0, K, k0, tid);
            asm volatile("cp.async.commit_group;" ::: "memory");
        }
        if (++buf == 3) buf = 0;
    }

    const int re = (int)row0 + wm * 64 + (lane >> 2);
    const int ce = (int)col0 + wn * 64 + (lane & 3) * 2;
    #pragma unroll
    for (int am = 0; am < 4; am++) {
        #pragma unroll
        for (int an = 0; an < 8; an++) {
            const int r = re + am * 16;
            const int c = ce + an * 8;
            float v0 = acc[am][an][0] + bias[c];
            float v1 = acc[am][an][1] + bias[c + 1];
            float v2 = acc[am][an][2] + bias[c];
            float v3 = acc[am][an][3] + bias[c + 1];
            __nv_bfloat16 h0 = __float2bfloat16(v0), h1 = __float2bfloat16(v1);
            __nv_bfloat16 h2 = __float2bfloat16(v2), h3 = __float2bfloat16(v3);
            __nv_bfloat162 lp0 = __floats2bfloat162_rn(v0 - __bfloat162float(h0),
                                                       v1 - __bfloat162float(h1));
            __nv_bfloat162 lp1 = __floats2bfloat162_rn(v2 - __bfloat162float(h2),
                                                       v3 - __bfloat162float(h3));
            uint32_t hp0 = (uint32_t)__bfloat16_as_ushort(h0) |
                           ((uint32_t)__bfloat16_as_ushort(h1) << 16);
            uint32_t hp1 = (uint32_t)__bfloat16_as_ushort(h2) |
                           ((uint32_t)__bfloat16_as_ushort(h3) << 16);
            *(uint32_t*)&Chi[(size_t)r * H_ + c]       = hp0;
            *(uint32_t*)&Chi[(size_t)(r + 8) * H_ + c] = hp1;
            *(uint32_t*)&Clo[(size_t)r * H_ + c]       = *reinterpret_cast<uint32_t*>(&lp0);
            *(uint32_t*)&Clo[(size_t)(r + 8) * H_ + c] = *reinterpret_cast<uint32_t*>(&lp1);
        }
    }
}

// ===========================================================================
// gemm_sym: graph[b] = s[b] @ s[b]^T (fp32), upper-tri tiles + mirror write.
// Block 128x128, warp 64x32, KC=32, 3-stage ring, 2 CTAs/SM.
// (R10 structure; MMA loops reordered product-major)
// ===========================================================================
#define S_ALO 8192
#define S_BHI 16384
#define S_BLO 24576
#define S_STG 32768
#define S_SMEM (3 * S_STG)

__global__ __launch_bounds__(256, 2)
void gemm_sym(const __nv_bfloat16* __restrict__ sh, const __nv_bfloat16* __restrict__ sl,
              float* __restrict__ G)
{
    extern __shared__ __align__(1024) char smem[];
    const uint32_t sb = smem_u32(smem);
    const int tid = threadIdx.x;
    const int bz  = blockIdx.z;
    const int K = H_;

    int by = 0, rem = blockIdx.x;
    #pragma unroll
    for (int i = 0; i < 8; i++) {
        if (rem >= 8 - by) { rem -= (8 - by); by++; }
    }
    const int bx = by + rem;

    const __nv_bfloat16* Ahi = sh + (size_t)bz * L_ * H_;
    const __nv_bfloat16* Alo = sl + (size_t)bz * L_ * H_;
    float* Gb = G + (size_t)bz * L_ * L_;

    const size_t row0 = (size_t)by * 128;
    const size_t col0 = (size_t)bx * 128;

    const int lane = tid & 31, warp = tid >> 5;
    const int wm = warp >> 2, wn = warp & 3;

    const uint32_t dlA = (uint32_t)((lane & 15) >> 1);
    const uint32_t baseA = (uint32_t)(wm * 32 + dlA) * 128;
    uint32_t chA[2];
    #pragma unroll
    for (int ks = 0; ks < 2; ks++)
        chA[ks] = ((((uint32_t)(lane & 1) << 2) + (uint32_t)(2 * ks + (lane >> 4))) ^ dlA) << 4;
    const uint32_t vB  = (uint32_t)((lane & 7) | ((lane >> 4) << 3));
    const uint32_t dlB = vB >> 1;
    const uint32_t baseB = (uint32_t)(wn * 16 + dlB) * 128;
    uint32_t chB[2];
    #pragma unroll
    for (int ks = 0; ks < 2; ks++)
        chB[ks] = ((((uint32_t)(lane & 1) << 2) + (uint32_t)(2 * ks + ((lane >> 3) & 1))) ^ dlB) << 4;

    float acc[4][4][4];
    #pragma unroll
    for (int i = 0; i < 4; i++)
        #pragma unroll
        for (int j = 0; j < 4; j++)
            #pragma unroll
            for (int q = 0; q < 4; q++) acc[i][j][q] = 0.0f;

    const int NS = K / 32;
    {
        uint32_t s0 = sb, s1 = sb + S_STG;
        stage_rows<2>(s0 + 0,     Ahi, row0, K, 0, tid);
        stage_rows<2>(s0 + S_ALO, Alo, row0, K, 0, tid);
        stage_rows<2>(s0 + S_BHI, Ahi, col0, K, 0, tid);
        stage_rows<2>(s0 + S_BLO, Alo, col0, K, 0, tid);
        asm volatile("cp.async.commit_group;" ::: "memory");
        stage_rows<2>(s1 + 0,     Ahi, row0, K, 32, tid);
        stage_rows<2>(s1 + S_ALO, Alo, row0, K, 32, tid);
        stage_rows<2>(s1 + S_BHI, Ahi, col0, K, 32, tid);
        stage_rows<2>(s1 + S_BLO, Alo, col0, K, 32, tid);
        asm volatile("cp.async.commit_group;" ::: "memory");
    }

    int buf = 0;
    for (int st = 0; st < NS; st++) {
        if (st + 1 < NS) asm volatile("cp.async.wait_group 1;" ::: "memory");
        else             asm volatile("cp.async.wait_group 0;" ::: "memory");
        __syncthreads();

        const uint32_t sbuf = sb + (uint32_t)buf * S_STG;
        #pragma unroll
        for (int ks = 0; ks < 2; ks++) {
            uint32_t ah[4][4], al[4][4];
            #pragma unroll
            for (int am = 0; am < 4; am++) {
                ldsm4(sbuf + baseA + am * 1024 + chA[ks],
                      ah[am][0], ah[am][1], ah[am][2], ah[am][3]);
                ldsm4(sbuf + S_ALO + baseA + am * 1024 + chA[ks],
                      al[am][0], al[am][1], al[am][2], al[am][3]);
            }
            uint32_t bh[4][2], bl[4][2];
            #pragma unroll
            for (int p = 0; p < 2; p++) {
                uint32_t r0, r1, r2, r3;
                ldsm4(sbuf + S_BHI + baseB + p * 1024 + chB[ks], r0, r1, r2, r3);
                bh[2 * p][0] = r0; bh[2 * p][1] = r1;
                bh[2 * p + 1][0] = r2; bh[2 * p + 1][1] = r3;
                ldsm4(sbuf + S_BLO + baseB + p * 1024 + chB[ks], r0, r1, r2, r3);
                bl[2 * p][0] = r0; bl[2 * p][1] = r1;
                bl[2 * p + 1][0] = r2; bl[2 * p + 1][1] = r3;
            }
            // product-major ordering
            #pragma unroll
            for (int am = 0; am < 4; am++)
                #pragma unroll
                for (int an = 0; an < 4; an++)
                    mma16816(acc[am][an], ah[am], bh[an]);
            #pragma unroll
            for (int am = 0; am < 4; am++)
                #pragma unroll
                for (int an = 0; an < 4; an++)
                    mma16816(acc[am][an], ah[am], bl[an]);
            #pragma unroll
            for (int am = 0; am < 4; am++)
                #pragma unroll
                for (int an = 0; an < 4; an++)
                    mma16816(acc[am][an], al[am], bh[an]);
        }

        if (st + 2 < NS) {
            int nb = buf + 2; if (nb >= 3) nb -= 3;
            const uint32_t np = sb + (uint32_t)nb * S_STG;
            const int k0 = (st + 2) * 32;
            stage_rows<2>(np + 0,     Ahi, row0, K, k0, tid);
            stage_rows<2>(np + S_ALO, Alo, row0, K, k0, tid);
            stage_rows<2>(np + S_BHI, Ahi, col0, K, k0, tid);
            stage_rows<2>(np + S_BLO, Alo, col0, K, k0, tid);
            asm volatile("cp.async.commit_group;" ::: "memory");
        }
        if (++buf == 3) buf = 0;
    }

    // all warps must finish reading the smem ring before it is reused below
    __syncthreads();

    const int rl = wm * 64 + (lane >> 2);
    const int cl = wn * 32 + (lane & 3) * 2;
    float* eb = (float*)smem;     // 128 x 129 fp32 staging
    #pragma unroll
    for (int am = 0; am < 4; am++) {
        #pragma unroll
        for (int an = 0; an < 4; an++) {
            const int r = rl + am * 16;
            const int c = cl + an * 8;
            float v0 = acc[am][an][0], v1 = acc[am][an][1];
            float v2 = acc[am][an][2], v3 = acc[am][an][3];
            *(float2*)&Gb[(row0 + r) * L_ + col0 + c]     = make_float2(v0, v1);
            *(float2*)&Gb[(row0 + r + 8) * L_ + col0 + c] = make_float2(v2, v3);
            if (bx != by) {
                eb[r * 129 + c] = v0;       eb[r * 129 + c + 1] = v1;
                eb[(r + 8) * 129 + c] = v2; eb[(r + 8) * 129 + c + 1] = v3;
            }
        }
    }
    if (bx != by) {
        __syncthreads();
        #pragma unroll 4
        for (int it = 0; it < 64; it++) {
            int idx = tid + it * 256;
            int j = idx >> 7, i = idx & 127;
            Gb[(col0 + j) * L_ + row0 + i] = eb[i * 129 + j];
        }
    }
}

// ---------------------------------------------------------------------------
// Row softmax, diag masked; emits A as bf16 hi/lo.
// ---------------------------------------------------------------------------
__global__ __launch_bounds__(256)
void softmax_kernel(const float* __restrict__ G, __nv_bfloat16* __restrict__ Ah,
                    __nv_bfloat16* __restrict__ Al)
{
    const int l = blockIdx.x;
    const int b = blockIdx.y;
    const size_t rowoff = ((size_t)b * L_ + (size_t)l) * L_;
    const int tid = threadIdx.x;

    float4 v = ((const float4*)(G + rowoff))[tid];
    if ((l >> 2) == tid) (&v.x)[l & 3] -= 1e5f;

    float mx = fmaxf(fmaxf(v.x, v.y), fmaxf(v.z, v.w));

    __shared__ float red1[8];
    __shared__ float red2[8];
    #pragma unroll
    for (int o = 16; o > 0; o >>= 1)
        mx = fmaxf(mx, __shfl_xor_sync(0xffffffffu, mx, o));
    if ((tid & 31) == 0) red1[tid >> 5] = mx;
    __syncthreads();
    mx = red1[0];
    #pragma unroll
    for (int i = 1; i < 8; i++) mx = fmaxf(mx, red1[i]);

    v.x = __expf(v.x - mx); v.y = __expf(v.y - mx);
    v.z = __expf(v.z - mx); v.w = __expf(v.w - mx);
    float s = (v.x + v.y) + (v.z + v.w);
    #pragma unroll
    for (int o = 16; o > 0; o >>= 1)
        s += __shfl_xor_sync(0xffffffffu, s, o);
    if ((tid & 31) == 0) red2[tid >> 5] = s;
    __syncthreads();
    s = red2[0];
    #pragma unroll
    for (int i = 1; i < 8; i++) s += red2[i];

    const float inv = 1.0f / s;
    v.x *= inv; v.y *= inv; v.z *= inv; v.w *= inv;

    __nv_bfloat16 h0 = __float2bfloat16(v.x), h1 = __float2bfloat16(v.y);
    __nv_bfloat16 h2 = __float2bfloat16(v.z), h3 = __float2bfloat16(v.w);
    float l0 = v.x - __bfloat162float(h0);
    float l1 = v.y - __bfloat162float(h1);
    float l2 = v.z - __bfloat162float(h2);
    float l3 = v.w - __bfloat162float(h3);
    uint2 hv, lv;
    hv.x = (uint32_t)__bfloat16_as_ushort(h0) | ((uint32_t)__bfloat16_as_ushort(h1) << 16);
    hv.y = (uint32_t)__bfloat16_as_ushort(h2) | ((uint32_t)__bfloat16_as_ushort(h3) << 16);
    __nv_bfloat162 p01 = __floats2bfloat162_rn(l0, l1);
    __nv_bfloat162 p23 = __floats2bfloat162_rn(l2, l3);
    lv.x = *reinterpret_cast<uint32_t*>(&p01);
    lv.y = *reinterpret_cast<uint32_t*>(&p23);
    ((uint2*)(Ah + rowoff))[tid] = hv;
    ((uint2*)(Al + rowoff))[tid] = lv;
}

// ---------------------------------------------------------------------------
// B0 = (sup - colsum/total) * row_has (fp32);  u1 = B0 as bf16 hi/lo.
// ---------------------------------------------------------------------------
__global__ __launch_bounds__(1024)
void b0_kernel(const float* __restrict__ lab, float* __restrict__ B0,
               __nv_bfloat16* __restrict__ uh, __nv_bfloat16* __restrict__ ul)
{
    const int b = blockIdx.x;
    const int t = threadIdx.x;
    const float* supb = lab + (size_t)b * L_ * N_;

    __shared__ float colp[16][64];
    __shared__ float s_col[64];
    __shared__ float s_rh[L_];
    __shared__ float s_tot;

    if (t == 0) s_tot = 0.0f;

    {
        const int c = t & 63, g = t >> 6;
        float cp = 0.0f;
        #pragma unroll 4
        for (int i = 0; i < 64; i++)
            cp += supb[(size_t)(i * 16 + g) * N_ + c];
        colp[g][c] = cp;
    }
    {
        const int w = t >> 5, lane = t & 31;
        for (int r = w; r < L_; r += 32) {
            float v = supb[(size_t)r * N_ + lane] + supb[(size_t)r * N_ + 32 + lane];
            #pragma unroll
            for (int o = 16; o > 0; o >>= 1) v += __shfl_xor_sync(0xffffffffu, v, o);
            if (lane == 0) s_rh[r] = (v > 0.5f) ? 1.0f : 0.0f;
        }
    }
    __syncthreads();
    if (t < 64) {
        float s = 0.0f;
        #pragma unroll
        for (int j = 0; j < 16; j++) s += colp[j][t];
        s_col[t] = s;
    }
    {
        float v = s_rh[t];
        #pragma unroll
        for (int o = 16; o > 0; o >>= 1) v += __shfl_xor_sync(0xffffffffu, v, o);
        if ((t & 31) == 0) atomicAdd(&s_tot, v);
    }
    __syncthreads();

    const float inv = 1.0f / s_tot;
    const size_t boff = (size_t)b * L_ * N_;
    #pragma unroll 4
    for (int i = 0; i < 64; i++) {
        const int idx = t + i * 1024;
        const int r = idx >> 6, n = idx & 63;
        float v = (supb[idx] - s_col[n] * inv) * s_rh[r];
        B0[boff + idx] = v;
        __nv_bfloat16 h = __float2bfloat16(v);
        uh[boff + idx] = h;
        ul[boff + idx] = __float2bfloat16(v - __bfloat162float(h));
    }
}

// ---------------------------------------------------------------------------
// Tensor-core power-iteration step (3-stage ring; product-major MMA order).
// ---------------------------------------------------------------------------
#define IT_KC   32
#define IT_AL_OFF 8192
#define IT_UH_OFF 16384
#define IT_UL_OFF 20480
#define IT_STG  24576
#define IT_SMEM (3 * IT_STG)

__device__ __forceinline__ void it_stage(uint32_t sbuf,
        const __nv_bfloat16* __restrict__ Ah, const __nv_bfloat16* __restrict__ Al,
        const __nv_bfloat16* __restrict__ uh, const __nv_bfloat16* __restrict__ ul,
        int l0, int k0, int tid)
{
    #pragma unroll
    for (int i = 0; i < 2; i++) {
        int idx = tid + i * 256;
        int r = idx >> 4, c = idx & 15;
        uint32_t off = (uint32_t)r * 256 + ((uint32_t)(c ^ (r & 15)) << 4);
        const void* gp = Ah + (size_t)(k0 + r) * L_ + l0 + c * 8;
        cp16(sbuf + off, gp);
        const void* gq = Al + (size_t)(k0 + r) * L_ + l0 + c * 8;
        cp16(sbuf + IT_AL_OFF + off, gq);
    }
    {
        int r = tid >> 3, c = tid & 7;
        uint32_t off = (uint32_t)r * 128 + ((uint32_t)(c ^ (r & 7)) << 4);
        cp16(sbuf + IT_UH_OFF + off, uh + (size_t)(k0 + r) * N_ + c * 8);
        cp16(sbuf + IT_UL_OFF + off, ul + (size_t)(k0 + r) * N_ + c * 8);
    }
    asm volatile("cp.async.commit_group;" ::: "memory");
}

template<int LAST>
__global__ __launch_bounds__(256, 2)
void iter_mma(const __nv_bfloat16* __restrict__ Ah, const __nv_bfloat16* __restrict__ Al,
              const __nv_bfloat16* __restrict__ uh_in, const __nv_bfloat16* __restrict__ ul_in,
              const float* __restrict__ B0, const float* __restrict__ pred,
              __nv_bfloat16* __restrict__ uh_out, __nv_bfloat16* __restrict__ ul_out,
              float* __restrict__ f32out)
{
    extern __shared__ __align__(1024) char smem[];
    const uint32_t sb = smem_u32(smem);
    const int tid = threadIdx.x;
    const int b = blockIdx.z;
    const int l0 = blockIdx.x * 128;

    const __nv_bfloat16* Ahb = Ah + (size_t)b * L_ * L_;
    const __nv_bfloat16* Alb = Al + (size_t)b * L_ * L_;
    const __nv_bfloat16* uhb = uh_in + (size_t)b * L_ * N_;
    const __nv_bfloat16* ulb = ul_in + (size_t)b * L_ * N_;

    const int lane = tid & 31, warp = tid >> 5;
    const int wm = warp >> 2, wn = warp & 3;

    uint32_t aoff[2][4];
    {
        uint32_t k_lane = (uint32_t)((lane & 7) + ((lane >> 4) << 3));
        uint32_t mbit = (uint32_t)((lane >> 3) & 1);
        #pragma unroll
        for (int ks = 0; ks < 2; ks++) {
            uint32_t k = (uint32_t)(ks * 16) + k_lane;
            #pragma unroll
            for (int am = 0; am < 4; am++) {
                uint32_t cA = (uint32_t)(wm * 8 + am * 2) + mbit;
                aoff[ks][am] = k * 256 + ((cA ^ (k & 15)) << 4);
            }
        }
    }
    uint32_t uoff[2];
    {
        uint32_t k_lane = (uint32_t)((lane & 7) + (((lane >> 3) & 1) << 3));
        uint32_t cn = (uint32_t)(wn * 2 + (lane >> 4));
        #pragma unroll
        for (int ks = 0; ks < 2; ks++) {
            uint32_t k = (uint32_t)(ks * 16) + k_lane;
            uoff[ks] = k * 128 + ((cn ^ (k & 7)) << 4);
        }
    }

    float acc[4][2][4];
    #pragma unroll
    for (int i = 0; i < 4; i++)
        #pragma unroll
        for (int j = 0; j < 2; j++)
            #pragma unroll
            for (int q = 0; q < 4; q++) acc[i][j][q] = 0.0f;

    const int NS = L_ / IT_KC;
    it_stage(sb + 0 * IT_STG, Ahb, Alb, uhb, ulb, l0, 0,      tid);
    it_stage(sb + 1 * IT_STG, Ahb, Alb, uhb, ulb, l0, IT_KC,  tid);

    int buf = 0;
    for (int st = 0; st < NS; st++) {
        if (st + 1 < NS) asm volatile("cp.async.wait_group 1;" ::: "memory");
        else             asm volatile("cp.async.wait_group 0;" ::: "memory");
        __syncthreads();

        const uint32_t sbuf = sb + (uint32_t)buf * IT_STG;
        #pragma unroll
        for (int ks = 0; ks < 2; ks++) {
            uint32_t ah[4][4], al4[4][4];
            #pragma unroll
            for (int am = 0; am < 4; am++) {
                ldsm4t(sbuf + aoff[ks][am],
                       ah[am][0], ah[am][1], ah[am][2], ah[am][3]);
                ldsm4t(sbuf + IT_AL_OFF + aoff[ks][am],
                       al4[am][0], al4[am][1], al4[am][2], al4[am][3]);
            }
            uint32_t bh[2][2], bl[2][2];
            {
                uint32_t r0, r1, r2, r3;
                ldsm4t(sbuf + IT_UH_OFF + uoff[ks], r0, r1, r2, r3);
                bh[0][0] = r0; bh[0][1] = r1; bh[1][0] = r2; bh[1][1] = r3;
                ldsm4t(sbuf + IT_UL_OFF + uoff[ks], r0, r1, r2, r3);
                bl[0][0] = r0; bl[0][1] = r1; bl[1][0] = r2; bl[1][1] = r3;
            }
            // product-major ordering
            #pragma unroll
            for (int am = 0; am < 4; am++)
                #pragma unroll
                for (int an = 0; an < 2; an++)
                    mma16816(acc[am][an], ah[am], bh[an]);
            #pragma unroll
            for (int am = 0; am < 4; am++)
                #pragma unroll
                for (int an = 0; an < 2; an++)
                    mma16816(acc[am][an], ah[am], bl[an]);
            #pragma unroll
            for (int am = 0; am < 4; am++)
                #pragma unroll
                for (int an = 0; an < 2; an++)
                    mma16816(acc[am][an], al4[am], bh[an]);
        }

        if (st + 2 < NS) {
            int nb = buf + 2; if (nb >= 3) nb -= 3;
            it_stage(sb + (uint32_t)nb * IT_STG, Ahb, Alb, uhb, ulb,
                     l0, (st + 2) * IT_KC, tid);
        }
        if (++buf == 3) buf = 0;
    }

    const int lbase = l0 + wm * 64 + (lane >> 2);
    const int nbase = wn * 16 + (lane & 3) * 2;
    #pragma unroll
    for (int am = 0; am < 4; am++) {
        #pragma unroll
        for (int an = 0; an < 2; an++) {
            const int l = lbase + am * 16;
            const int n = nbase + an * 8;
            const size_t o0 = ((size_t)b * L_ + l) * N_ + n;
            const size_t o1 = o0 + 8 * N_;
            float v0 = acc[am][an][0] + B0[o0];
            float v1 = acc[am][an][1] + B0[o0 + 1];
            float v2 = acc[am][an][2] + B0[o1];
            float v3 = acc[am][an][3] + B0[o1 + 1];
            if (pred) {
                v0 += pred[o0]; v1 += pred[o0 + 1];
                v2 += pred[o1]; v3 += pred[o1 + 1];
            }
            if (LAST) {
                *(float2*)&f32out[o0] = make_float2(v0, v1);
                *(float2*)&f32out[o1] = make_float2(v2, v3);
            } else {
                __nv_bfloat16 h0 = __float2bfloat16(v0), h1 = __float2bfloat16(v1);
                __nv_bfloat16 h2 = __float2bfloat16(v2), h3 = __float2bfloat16(v3);
                __nv_bfloat162 lo01 = __floats2bfloat162_rn(v0 - __bfloat162float(h0),
                                                            v1 - __bfloat162float(h1));
                __nv_bfloat162 lo23 = __floats2bfloat162_rn(v2 - __bfloat162float(h2),
                                                            v3 - __bfloat162float(h3));
                uint32_t hp0 = (uint32_t)__bfloat16_as_ushort(h0) |
                               ((uint32_t)__bfloat16_as_ushort(h1) << 16);
                uint32_t hp1 = (uint32_t)__bfloat16_as_ushort(h2) |
                               ((uint32_t)__bfloat16_as_ushort(h3) << 16);
                *(uint32_t*)&uh_out[o0] = hp0;
                *(uint32_t*)&uh_out[o1] = hp1;
                *(uint32_t*)&ul_out[o0] = *reinterpret_cast<uint32_t*>(&lo01);
                *(uint32_t*)&ul_out[o1] = *reinterpret_cast<uint32_t*>(&lo23);
            }
        }
    }
}

// ---------------------------------------------------------------------------
extern "C" void kernel_launch(void* const* d_in, const int* in_sizes, int n_in,
                              void* d_out, int out_size)
{
    const float* samples = (const float*)d_in[0];  // [8,1024,3072]
    const float* label   = (const float*)d_in[1];  // [8,1024,64]
    const float* predict = (const float*)d_in[2];  // [8,1024,64]
    const float* W       = (const float*)d_in[3];  // [1024,3072]
    const float* bproj   = (const float*)d_in[4];  // [1024]
    float* out = (float*)d_out;                    // [8,1024,64]

    __nv_bfloat16 *smph, *smpl, *Wh, *Wl, *sh, *sl, *uh1, *ul1, *uh2, *ul2;
    float *A, *B0;
    cudaGetSymbolAddress((void**)&smph, g_smp_hi);
    cudaGetSymbolAddress((void**)&smpl, g_smp_lo);
    cudaGetSymbolAddress((void**)&Wh,   g_W_hi);
    cudaGetSymbolAddress((void**)&Wl,   g_W_lo);
    cudaGetSymbolAddress((void**)&sh,   g_s_hi);
    cudaGetSymbolAddress((void**)&sl,   g_s_lo);
    cudaGetSymbolAddress((void**)&A,    g_A);
    cudaGetSymbolAddress((void**)&B0,   g_B0);
    cudaGetSymbolAddress((void**)&uh1,  g_uh1);
    cudaGetSymbolAddress((void**)&ul1,  g_ul1);
    cudaGetSymbolAddress((void**)&uh2,  g_uh2);
    cudaGetSymbolAddress((void**)&ul2,  g_ul2);

    cudaFuncSetAttribute(gemm_proj, cudaFuncAttributeMaxDynamicSharedMemorySize, P_SMEM);
    cudaFuncSetAttribute(gemm_sym,  cudaFuncAttributeMaxDynamicSharedMemorySize, S_SMEM);
    cudaFuncSetAttribute(iter_mma<0>, cudaFuncAttributeMaxDynamicSharedMemorySize, IT_SMEM);
    cudaFuncSetAttribute(iter_mma<1>, cudaFuncAttributeMaxDynamicSharedMemorySize, IT_SMEM);

    {
        int n4 = (B_ * L_ * K3_) / 4;
        split_kernel<<<(n4 + 255) / 256, 256>>>(samples, smph, smpl, n4);
        int w4 = (H_ * K3_) / 4;
        split_kernel<<<(w4 + 255) / 256, 256>>>(W, Wh, Wl, w4);
    }

    gemm_proj<<<dim3(H_ / 256, (B_ * L_) / 128, 1), 256, P_SMEM>>>(
        smph, smpl, Wh, Wl, bproj, sh, sl);

    gemm_sym<<<dim3(36, 1, B_), 256, S_SMEM>>>(sh, sl, A);

    softmax_kernel<<<dim3(L_, B_), 256>>>(A, sh, sl);

    b0_kernel<<<B_, 1024>>>(label, B0, uh1, ul1);

    dim3 ig(L_ / 128, 1, B_);
    iter_mma<0><<<ig, 256, IT_SMEM>>>(sh, sl, uh1, ul1, B0, nullptr,  uh2, ul2, nullptr); // t=2
    iter_mma<0><<<ig, 256, IT_SMEM>>>(sh, sl, uh2, ul2, B0, predict,  uh1, ul1, nullptr); // t=3
    iter_mma<0><<<ig, 256, IT_SMEM>>>(sh, sl, uh1, ul1, B0, nullptr,  uh2, ul2, nullptr); // t=4
    iter_mma<0><<<ig, 256, IT_SMEM>>>(sh, sl, uh2, ul2, B0, nullptr,  uh1, ul1, nullptr); // t=5
    iter_mma<1><<<ig, 256, IT_SMEM>>>(sh, sl, uh1, ul1, B0, nullptr,  nullptr, nullptr, out); // t=6
}

// round 14
// speedup vs baseline: 1.1476x; 1.0809x over previous
#include <cuda_runtime.h>
#include <cuda_bf16.h>
#include <cstddef>
#include <cstdint>

#define B_  8
#define L_  1024
#define H_  1024
#define K3_ 3072
#define N_  64

// ---------------------------------------------------------------------------
// Static scratch (no allocations allowed)
// ---------------------------------------------------------------------------
__device__ __align__(256) __nv_bfloat16 g_smp_hi[(size_t)B_ * L_ * K3_];
__device__ __align__(256) __nv_bfloat16 g_smp_lo[(size_t)B_ * L_ * K3_];
__device__ __align__(256) __nv_bfloat16 g_W_hi [(size_t)H_ * K3_];
__device__ __align__(256) __nv_bfloat16 g_W_lo [(size_t)H_ * K3_];
__device__ __align__(256) __nv_bfloat16 g_s_hi [(size_t)B_ * L_ * H_];  // later: A_hi
__device__ __align__(256) __nv_bfloat16 g_s_lo [(size_t)B_ * L_ * H_];  // later: A_lo
__device__ __align__(256) float g_A [(size_t)B_ * L_ * L_];             // graph (fp32)
__device__ __align__(256) float g_B0[(size_t)B_ * L_ * N_];
__device__ __align__(256) __nv_bfloat16 g_uh1[(size_t)B_ * L_ * N_];
__device__ __align__(256) __nv_bfloat16 g_ul1[(size_t)B_ * L_ * N_];
__device__ __align__(256) __nv_bfloat16 g_uh2[(size_t)B_ * L_ * N_];
__device__ __align__(256) __nv_bfloat16 g_ul2[(size_t)B_ * L_ * N_];

// ---------------------------------------------------------------------------
// PTX helpers (baseline-PTX only: cp.async / ldmatrix / mma.sync)
// ---------------------------------------------------------------------------
__device__ __forceinline__ uint32_t smem_u32(const void* p) {
    uint32_t a;
    asm("{ .reg .u64 t; cvta.to.shared.u64 t, %1; cvt.u32.u64 %0, t; }" : "=r"(a) : "l"(p));
    return a;
}

__device__ __forceinline__ void cp16(uint32_t saddr, const void* g) {
    asm volatile("cp.async.cg.shared.global [%0], [%1], 16;" :: "r"(saddr), "l"(g) : "memory");
}

__device__ __forceinline__ void ldsm4(uint32_t addr, uint32_t& r0, uint32_t& r1,
                                      uint32_t& r2, uint32_t& r3) {
    asm volatile("ldmatrix.sync.aligned.m8n8.x4.shared.b16 {%0,%1,%2,%3}, [%4];"
                 : "=r"(r0), "=r"(r1), "=r"(r2), "=r"(r3) : "r"(addr));
}

__device__ __forceinline__ void ldsm4t(uint32_t addr, uint32_t& r0, uint32_t& r1,
                                       uint32_t& r2, uint32_t& r3) {
    asm volatile("ldmatrix.sync.aligned.m8n8.x4.trans.shared.b16 {%0,%1,%2,%3}, [%4];"
                 : "=r"(r0), "=r"(r1), "=r"(r2), "=r"(r3) : "r"(addr));
}

__device__ __forceinline__ void mma16816(float* c, const uint32_t* a, const uint32_t* b) {
    asm volatile(
        "mma.sync.aligned.m16n8k16.row.col.f32.bf16.bf16.f32 "
        "{%0,%1,%2,%3}, {%4,%5,%6,%7}, {%8,%9}, {%0,%1,%2,%3};"
        : "+f"(c[0]), "+f"(c[1]), "+f"(c[2]), "+f"(c[3])
        : "r"(a[0]), "r"(a[1]), "r"(a[2]), "r"(a[3]), "r"(b[0]), "r"(b[1]));
}

// ---------------------------------------------------------------------------
// fp32 -> bf16 hi/lo split
// ---------------------------------------------------------------------------
__global__ __launch_bounds__(256)
void split_kernel(const float* __restrict__ x, __nv_bfloat16* __restrict__ hi,
                  __nv_bfloat16* __restrict__ lo, int n4)
{
    int i = blockIdx.x * blockDim.x + threadIdx.x;
    if (i >= n4) return;
    float4 v = ((const float4*)x)[i];
    __nv_bfloat16 h0 = __float2bfloat16(v.x), h1 = __float2bfloat16(v.y);
    __nv_bfloat16 h2 = __float2bfloat16(v.z), h3 = __float2bfloat16(v.w);
    float r0 = v.x - __bfloat162float(h0);
    float r1 = v.y - __bfloat162float(h1);
    float r2 = v.z - __bfloat162float(h2);
    float r3 = v.w - __bfloat162float(h3);
    uint2 hv, lv;
    hv.x = (uint32_t)__bfloat16_as_ushort(h0) | ((uint32_t)__bfloat16_as_ushort(h1) << 16);
    hv.y = (uint32_t)__bfloat16_as_ushort(h2) | ((uint32_t)__bfloat16_as_ushort(h3) << 16);
    __nv_bfloat162 l01 = __floats2bfloat162_rn(r0, r1);
    __nv_bfloat162 l23 = __floats2bfloat162_rn(r2, r3);
    lv.x = *reinterpret_cast<uint32_t*>(&l01);
    lv.y = *reinterpret_cast<uint32_t*>(&l23);
    ((uint2*)hi)[i] = hv;
    ((uint2*)lo)[i] = lv;
}

// ---------------------------------------------------------------------------
// Shared staging helper: (ITERS*64) rows x 32k bf16 tile, paired-row swizzle
// ---------------------------------------------------------------------------
template<int ITERS>
__device__ __forceinline__ void stage_rows(uint32_t sdst, const __nv_bfloat16* __restrict__ g,
                                           size_t row0, int ldk, int k0, int tid)
{
    #pragma unroll
    for (int i = 0; i < ITERS; i++) {
        int idx = tid + i * 256;
        int r = idx >> 2, c = idx & 3;
        const void* gp = g + (row0 + (size_t)r) * (size_t)ldk + k0 + c * 8;
        uint32_t line = (uint32_t)(r >> 1);
        uint32_t off = line * 128 + ((((uint32_t)(r & 1) * 4 + (uint32_t)c) ^ (line & 7)) << 4);
        cp16(sdst + off, gp);
    }
}

// ===========================================================================
// gemm_proj: s = samples @ W^T + bias -> bf16 hi/lo.  (R13 version, unchanged)
// Block 128(M) x 256(N), warp tile 64x64 (8 warps = 2x4), KC=32, 3-stage ring.
// ===========================================================================
#define P_ALO 8192
#define P_BHI 16384
#define P_BLO 32768
#define P_STG 49152
#define P_SMEM (3 * P_STG)

__global__ __launch_bounds__(256, 1)
void gemm_proj(const __nv_bfloat16* __restrict__ Ahi, const __nv_bfloat16* __restrict__ Alo,
               const __nv_bfloat16* __restrict__ Bhi, const __nv_bfloat16* __restrict__ Blo,
               const float* __restrict__ bias,
               __nv_bfloat16* __restrict__ Chi, __nv_bfloat16* __restrict__ Clo)
{
    extern __shared__ __align__(1024) char smem[];
    const uint32_t sb = smem_u32(smem);
    const int tid = threadIdx.x;
    const size_t row0 = (size_t)blockIdx.y * 128;
    const size_t col0 = (size_t)blockIdx.x * 256;
    const int K = K3_;

    const int lane = tid & 31, warp = tid >> 5;
    const int wm = warp >> 2, wn = warp & 3;

    const uint32_t dlA = (uint32_t)((lane & 15) >> 1);
    const uint32_t baseA = (uint32_t)(wm * 32 + dlA) * 128;
    uint32_t chA[2];
    #pragma unroll
    for (int ks = 0; ks < 2; ks++)
        chA[ks] = ((((uint32_t)(lane & 1) << 2) + (uint32_t)(2 * ks + (lane >> 4))) ^ dlA) << 4;
    const uint32_t vB  = (uint32_t)((lane & 7) | ((lane >> 4) << 3));
    const uint32_t dlB = vB >> 1;
    const uint32_t baseB = (uint32_t)(wn * 32 + dlB) * 128;
    uint32_t chB[2];
    #pragma unroll
    for (int ks = 0; ks < 2; ks++)
        chB[ks] = ((((uint32_t)(lane & 1) << 2) + (uint32_t)(2 * ks + ((lane >> 3) & 1))) ^ dlB) << 4;

    float acc[4][8][4];
    #pragma unroll
    for (int i = 0; i < 4; i++)
        #pragma unroll
        for (int j = 0; j < 8; j++)
            #pragma unroll
            for (int q = 0; q < 4; q++) acc[i][j][q] = 0.0f;

    const int NS = K / 32;
    {
        uint32_t s0 = sb, s1 = sb + P_STG;
        stage_rows<2>(s0 + 0,     Ahi, row0, K, 0, tid);
        stage_rows<2>(s0 + P_ALO, Alo, row0, K, 0, tid);
        stage_rows<4>(s0 + P_BHI, Bhi, col0, K, 0, tid);
        stage_rows<4>(s0 + P_BLO, Blo, col0, K, 0, tid);
        asm volatile("cp.async.commit_group;" ::: "memory");
        stage_rows<2>(s1 + 0,     Ahi, row0, K, 32, tid);
        stage_rows<2>(s1 + P_ALO, Alo, row0, K, 32, tid);
        stage_rows<4>(s1 + P_BHI, Bhi, col0, K, 32, tid);
        stage_rows<4>(s1 + P_BLO, Blo, col0, K, 32, tid);
        asm volatile("cp.async.commit_group;" ::: "memory");
    }

    int buf = 0;
    for (int st = 0; st < NS; st++) {
        if (st + 1 < NS) asm volatile("cp.async.wait_group 1;" ::: "memory");
        else             asm volatile("cp.async.wait_group 0;" ::: "memory");
        __syncthreads();

        const uint32_t sbuf = sb + (uint32_t)buf * P_STG;
        #pragma unroll
        for (int ks = 0; ks < 2; ks++) {
            uint32_t ah[4][4], al[4][4];
            #pragma unroll
            for (int am = 0; am < 4; am++) {
                ldsm4(sbuf + baseA + am * 1024 + chA[ks],
                      ah[am][0], ah[am][1], ah[am][2], ah[am][3]);
                ldsm4(sbuf + P_ALO + baseA + am * 1024 + chA[ks],
                      al[am][0], al[am][1], al[am][2], al[am][3]);
            }
            uint32_t bh[8][2], bl[8][2];
            #pragma unroll
            for (int p = 0; p < 4; p++) {
                uint32_t r0, r1, r2, r3;
                ldsm4(sbuf + P_BHI + baseB + p * 1024 + chB[ks], r0, r1, r2, r3);
                bh[2 * p][0] = r0; bh[2 * p][1] = r1;
                bh[2 * p + 1][0] = r2; bh[2 * p + 1][1] = r3;
                ldsm4(sbuf + P_BLO + baseB + p * 1024 + chB[ks], r0, r1, r2, r3);
                bl[2 * p][0] = r0; bl[2 * p][1] = r1;
                bl[2 * p + 1][0] = r2; bl[2 * p + 1][1] = r3;
            }
            #pragma unroll
            for (int am = 0; am < 4; am++)
                #pragma unroll
                for (int an = 0; an < 8; an++)
                    mma16816(acc[am][an], ah[am], bh[an]);
            #pragma unroll
            for (int am = 0; am < 4; am++)
                #pragma unroll
                for (int an = 0; an < 8; an++)
                    mma16816(acc[am][an], ah[am], bl[an]);
            #pragma unroll
            for (int am = 0; am < 4; am++)
                #pragma unroll
                for (int an = 0; an < 8; an++)
                    mma16816(acc[am][an], al[am], bh[an]);
        }

        if (st + 2 < NS) {
            int nb = buf + 2; if (nb >= 3) nb -= 3;
            const uint32_t np = sb + (uint32_t)nb * P_STG;
            const int k0 = (st + 2) * 32;
            stage_rows<2>(np + 0,     Ahi, row0, K, k0, tid);
            stage_rows<2>(np + P_ALO, Alo, row0, K, k0, tid);
            stage_rows<4>(np + P_BHI, Bhi, col0, K, k0, tid);
            stage_rows<4>(np + P_BLO, Blo, col0, K, k0, tid);
            asm volatile("cp.async.commit_group;" ::: "memory");
        }
        if (++buf == 3) buf = 0;
    }

    const int re = (int)row0 + wm * 64 + (lane >> 2);
    const int ce = (int)col0 + wn * 64 + (lane & 3) * 2;
    #pragma unroll
    for (int am = 0; am < 4; am++) {
        #pragma unroll
        for (int an = 0; an < 8; an++) {
            const int r = re + am * 16;
            const int c = ce + an * 8;
            float v0 = acc[am][an][0] + bias[c];
            float v1 = acc[am][an][1] + bias[c + 1];
            float v2 = acc[am][an][2] + bias[c];
            float v3 = acc[am][an][3] + bias[c + 1];
            __nv_bfloat16 h0 = __float2bfloat16(v0), h1 = __float2bfloat16(v1);
            __nv_bfloat16 h2 = __float2bfloat16(v2), h3 = __float2bfloat16(v3);
            __nv_bfloat162 lp0 = __floats2bfloat162_rn(v0 - __bfloat162float(h0),
                                                       v1 - __bfloat162float(h1));
            __nv_bfloat162 lp1 = __floats2bfloat162_rn(v2 - __bfloat162float(h2),
                                                       v3 - __bfloat162float(h3));
            uint32_t hp0 = (uint32_t)__bfloat16_as_ushort(h0) |
                           ((uint32_t)__bfloat16_as_ushort(h1) << 16);
            uint32_t hp1 = (uint32_t)__bfloat16_as_ushort(h2) |
                           ((uint32_t)__bfloat16_as_ushort(h3) << 16);
            *(uint32_t*)&Chi[(size_t)r * H_ + c]       = hp0;
            *(uint32_t*)&Chi[(size_t)(r + 8) * H_ + c] = hp1;
            *(uint32_t*)&Clo[(size_t)r * H_ + c]       = *reinterpret_cast<uint32_t*>(&lp0);
            *(uint32_t*)&Clo[(size_t)(r + 8) * H_ + c] = *reinterpret_cast<uint32_t*>(&lp1);
        }
    }
}

// ===========================================================================
// gemm_sym: graph[b] = s[b] @ s[b]^T (fp32), upper-tri tiles + mirror write.
// Block 128x128, warp 64x32, KC=32, 3-stage ring, 2 CTAs/SM. (R13, unchanged)
// ===========================================================================
#define S_ALO 8192
#define S_BHI 16384
#define S_BLO 24576
#define S_STG 32768
#define S_SMEM (3 * S_STG)

__global__ __launch_bounds__(256, 2)
void gemm_sym(const __nv_bfloat16* __restrict__ sh, const __nv_bfloat16* __restrict__ sl,
              float* __restrict__ G)
{
    extern __shared__ __align__(1024) char smem[];
    const uint32_t sb = smem_u32(smem);
    const int tid = threadIdx.x;
    const int bz  = blockIdx.z;
    const int K = H_;

    int by = 0, rem = blockIdx.x;
    #pragma unroll
    for (int i = 0; i < 8; i++) {
        if (rem >= 8 - by) { rem -= (8 - by); by++; }
    }
    const int bx = by + rem;

    const __nv_bfloat16* Ahi = sh + (size_t)bz * L_ * H_;
    const __nv_bfloat16* Alo = sl + (size_t)bz * L_ * H_;
    float* Gb = G + (size_t)bz * L_ * L_;

    const size_t row0 = (size_t)by * 128;
    const size_t col0 = (size_t)bx * 128;

    const int lane = tid & 31, warp = tid >> 5;
    const int wm = warp >> 2, wn = warp & 3;

    const uint32_t dlA = (uint32_t)((lane & 15) >> 1);
    const uint32_t baseA = (uint32_t)(wm * 32 + dlA) * 128;
    uint32_t chA[2];
    #pragma unroll
    for (int ks = 0; ks < 2; ks++)
        chA[ks] = ((((uint32_t)(lane & 1) << 2) + (uint32_t)(2 * ks + (lane >> 4))) ^ dlA) << 4;
    const uint32_t vB  = (uint32_t)((lane & 7) | ((lane >> 4) << 3));
    const uint32_t dlB = vB >> 1;
    const uint32_t baseB = (uint32_t)(wn * 16 + dlB) * 128;
    uint32_t chB[2];
    #pragma unroll
    for (int ks = 0; ks < 2; ks++)
        chB[ks] = ((((uint32_t)(lane & 1) << 2) + (uint32_t)(2 * ks + ((lane >> 3) & 1))) ^ dlB) << 4;

    float acc[4][4][4];
    #pragma unroll
    for (int i = 0; i < 4; i++)
        #pragma unroll
        for (int j = 0; j < 4; j++)
            #pragma unroll
            for (int q = 0; q < 4; q++) acc[i][j][q] = 0.0f;

    const int NS = K / 32;
    {
        uint32_t s0 = sb, s1 = sb + S_STG;
        stage_rows<2>(s0 + 0,     Ahi, row0, K, 0, tid);
        stage_rows<2>(s0 + S_ALO, Alo, row0, K, 0, tid);
        stage_rows<2>(s0 + S_BHI, Ahi, col0, K, 0, tid);
        stage_rows<2>(s0 + S_BLO, Alo, col0, K, 0, tid);
        asm volatile("cp.async.commit_group;" ::: "memory");
        stage_rows<2>(s1 + 0,     Ahi, row0, K, 32, tid);
        stage_rows<2>(s1 + S_ALO, Alo, row0, K, 32, tid);
        stage_rows<2>(s1 + S_BHI, Ahi, col0, K, 32, tid);
        stage_rows<2>(s1 + S_BLO, Alo, col0, K, 32, tid);
        asm volatile("cp.async.commit_group;" ::: "memory");
    }

    int buf = 0;
    for (int st = 0; st < NS; st++) {
        if (st + 1 < NS) asm volatile("cp.async.wait_group 1;" ::: "memory");
        else             asm volatile("cp.async.wait_group 0;" ::: "memory");
        __syncthreads();

        const uint32_t sbuf = sb + (uint32_t)buf * S_STG;
        #pragma unroll
        for (int ks = 0; ks < 2; ks++) {
            uint32_t ah[4][4], al[4][4];
            #pragma unroll
            for (int am = 0; am < 4; am++) {
                ldsm4(sbuf + baseA + am * 1024 + chA[ks],
                      ah[am][0], ah[am][1], ah[am][2], ah[am][3]);
                ldsm4(sbuf + S_ALO + baseA + am * 1024 + chA[ks],
                      al[am][0], al[am][1], al[am][2], al[am][3]);
            }
            uint32_t bh[4][2], bl[4][2];
            #pragma unroll
            for (int p = 0; p < 2; p++) {
                uint32_t r0, r1, r2, r3;
                ldsm4(sbuf + S_BHI + baseB + p * 1024 + chB[ks], r0, r1, r2, r3);
                bh[2 * p][0] = r0; bh[2 * p][1] = r1;
                bh[2 * p + 1][0] = r2; bh[2 * p + 1][1] = r3;
                ldsm4(sbuf + S_BLO + baseB + p * 1024 + chB[ks], r0, r1, r2, r3);
                bl[2 * p][0] = r0; bl[2 * p][1] = r1;
                bl[2 * p + 1][0] = r2; bl[2 * p + 1][1] = r3;
            }
            #pragma unroll
            for (int am = 0; am < 4; am++)
                #pragma unroll
                for (int an = 0; an < 4; an++)
                    mma16816(acc[am][an], ah[am], bh[an]);
            #pragma unroll
            for (int am = 0; am < 4; am++)
                #pragma unroll
                for (int an = 0; an < 4; an++)
                    mma16816(acc[am][an], ah[am], bl[an]);
            #pragma unroll
            for (int am = 0; am < 4; am++)
                #pragma unroll
                for (int an = 0; an < 4; an++)
                    mma16816(acc[am][an], al[am], bh[an]);
        }

        if (st + 2 < NS) {
            int nb = buf + 2; if (nb >= 3) nb -= 3;
            const uint32_t np = sb + (uint32_t)nb * S_STG;
            const int k0 = (st + 2) * 32;
            stage_rows<2>(np + 0,     Ahi, row0, K, k0, tid);
            stage_rows<2>(np + S_ALO, Alo, row0, K, k0, tid);
            stage_rows<2>(np + S_BHI, Ahi, col0, K, k0, tid);
            stage_rows<2>(np + S_BLO, Alo, col0, K, k0, tid);
            asm volatile("cp.async.commit_group;" ::: "memory");
        }
        if (++buf == 3) buf = 0;
    }

    // all warps must finish reading the smem ring before it is reused below
    __syncthreads();

    const int rl = wm * 64 + (lane >> 2);
    const int cl = wn * 32 + (lane & 3) * 2;
    float* eb = (float*)smem;     // 128 x 129 fp32 staging
    #pragma unroll
    for (int am = 0; am < 4; am++) {
        #pragma unroll
        for (int an = 0; an < 4; an++) {
            const int r = rl + am * 16;
            const int c = cl + an * 8;
            float v0 = acc[am][an][0], v1 = acc[am][an][1];
            float v2 = acc[am][an][2], v3 = acc[am][an][3];
            *(float2*)&Gb[(row0 + r) * L_ + col0 + c]     = make_float2(v0, v1);
            *(float2*)&Gb[(row0 + r + 8) * L_ + col0 + c] = make_float2(v2, v3);
            if (bx != by) {
                eb[r * 129 + c] = v0;       eb[r * 129 + c + 1] = v1;
                eb[(r + 8) * 129 + c] = v2; eb[(r + 8) * 129 + c + 1] = v3;
            }
        }
    }
    if (bx != by) {
        __syncthreads();
        #pragma unroll 4
        for (int it = 0; it < 64; it++) {
            int idx = tid + it * 256;
            int j = idx >> 7, i = idx & 127;
            Gb[(col0 + j) * L_ + row0 + i] = eb[i * 129 + j];
        }
    }
}

// ---------------------------------------------------------------------------
// Row softmax, diag masked; emits A as bf16 hi/lo.
// ---------------------------------------------------------------------------
__global__ __launch_bounds__(256)
void softmax_kernel(const float* __restrict__ G, __nv_bfloat16* __restrict__ Ah,
                    __nv_bfloat16* __restrict__ Al)
{
    const int l = blockIdx.x;
    const int b = blockIdx.y;
    const size_t rowoff = ((size_t)b * L_ + (size_t)l) * L_;
    const int tid = threadIdx.x;

    float4 v = ((const float4*)(G + rowoff))[tid];
    if ((l >> 2) == tid) (&v.x)[l & 3] -= 1e5f;

    float mx = fmaxf(fmaxf(v.x, v.y), fmaxf(v.z, v.w));

    __shared__ float red1[8];
    __shared__ float red2[8];
    #pragma unroll
    for (int o = 16; o > 0; o >>= 1)
        mx = fmaxf(mx, __shfl_xor_sync(0xffffffffu, mx, o));
    if ((tid & 31) == 0) red1[tid >> 5] = mx;
    __syncthreads();
    mx = red1[0];
    #pragma unroll
    for (int i = 1; i < 8; i++) mx = fmaxf(mx, red1[i]);

    v.x = __expf(v.x - mx); v.y = __expf(v.y - mx);
    v.z = __expf(v.z - mx); v.w = __expf(v.w - mx);
    float s = (v.x + v.y) + (v.z + v.w);
    #pragma unroll
    for (int o = 16; o > 0; o >>= 1)
        s += __shfl_xor_sync(0xffffffffu, s, o);
    if ((tid & 31) == 0) red2[tid >> 5] = s;
    __syncthreads();
    s = red2[0];
    #pragma unroll
    for (int i = 1; i < 8; i++) s += red2[i];

    const float inv = 1.0f / s;
    v.x *= inv; v.y *= inv; v.z *= inv; v.w *= inv;

    __nv_bfloat16 h0 = __float2bfloat16(v.x), h1 = __float2bfloat16(v.y);
    __nv_bfloat16 h2 = __float2bfloat16(v.z), h3 = __float2bfloat16(v.w);
    float l0 = v.x - __bfloat162float(h0);
    float l1 = v.y - __bfloat162float(h1);
    float l2 = v.z - __bfloat162float(h2);
    float l3 = v.w - __bfloat162float(h3);
    uint2 hv, lv;
    hv.x = (uint32_t)__bfloat16_as_ushort(h0) | ((uint32_t)__bfloat16_as_ushort(h1) << 16);
    hv.y = (uint32_t)__bfloat16_as_ushort(h2) | ((uint32_t)__bfloat16_as_ushort(h3) << 16);
    __nv_bfloat162 p01 = __floats2bfloat162_rn(l0, l1);
    __nv_bfloat162 p23 = __floats2bfloat162_rn(l2, l3);
    lv.x = *reinterpret_cast<uint32_t*>(&p01);
    lv.y = *reinterpret_cast<uint32_t*>(&p23);
    ((uint2*)(Ah + rowoff))[tid] = hv;
    ((uint2*)(Al + rowoff))[tid] = lv;
}

// ---------------------------------------------------------------------------
// B0 = (sup - colsum/total) * row_has (fp32);  u1 = B0 as bf16 hi/lo.
// ---------------------------------------------------------------------------
__global__ __launch_bounds__(1024)
void b0_kernel(const float* __restrict__ lab, float* __restrict__ B0,
               __nv_bfloat16* __restrict__ uh, __nv_bfloat16* __restrict__ ul)
{
    const int b = blockIdx.x;
    const int t = threadIdx.x;
    const float* supb = lab + (size_t)b * L_ * N_;

    __shared__ float colp[16][64];
    __shared__ float s_col[64];
    __shared__ float s_rh[L_];
    __shared__ float s_tot;

    if (t == 0) s_tot = 0.0f;

    {
        const int c = t & 63, g = t >> 6;
        float cp = 0.0f;
        #pragma unroll 4
        for (int i = 0; i < 64; i++)
            cp += supb[(size_t)(i * 16 + g) * N_ + c];
        colp[g][c] = cp;
    }
    {
        const int w = t >> 5, lane = t & 31;
        for (int r = w; r < L_; r += 32) {
            float v = supb[(size_t)r * N_ + lane] + supb[(size_t)r * N_ + 32 + lane];
            #pragma unroll
            for (int o = 16; o > 0; o >>= 1) v += __shfl_xor_sync(0xffffffffu, v, o);
            if (lane == 0) s_rh[r] = (v > 0.5f) ? 1.0f : 0.0f;
        }
    }
    __syncthreads();
    if (t < 64) {
        float s = 0.0f;
        #pragma unroll
        for (int j = 0; j < 16; j++) s += colp[j][t];
        s_col[t] = s;
    }
    {
        float v = s_rh[t];
        #pragma unroll
        for (int o = 16; o > 0; o >>= 1) v += __shfl_xor_sync(0xffffffffu, v, o);
        if ((t & 31) == 0) atomicAdd(&s_tot, v);
    }
    __syncthreads();

    const float inv = 1.0f / s_tot;
    const size_t boff = (size_t)b * L_ * N_;
    #pragma unroll 4
    for (int i = 0; i < 64; i++) {
        const int idx = t + i * 1024;
        const int r = idx >> 6, n = idx & 63;
        float v = (supb[idx] - s_col[n] * inv) * s_rh[r];
        B0[boff + idx] = v;
        __nv_bfloat16 h = __float2bfloat16(v);
        uh[boff + idx] = h;
        ul[boff + idx] = __float2bfloat16(v - __bfloat162float(h));
    }
}

// ---------------------------------------------------------------------------
// Tensor-core power-iteration step — TM=64 tiles for full-chip coverage.
// Block: 64 l-rows x 64 n; 8 warps = 2(wm: 32l) x 4(wn: 16n).
// Grid (L/64, 1, B) = 128 CTAs (vs 64 before). A tiles: 32k x 64l (128B rows,
// swizzle c^(k&7) — same verified pattern as the u tiles). 3-stage ring.
// ---------------------------------------------------------------------------
#define IT_KC   32
#define IT_AL_OFF 4096
#define IT_UH_OFF 8192
#define IT_UL_OFF 12288
#define IT_STG  16384
#define IT_SMEM (3 * IT_STG)

__device__ __forceinline__ void it_stage(uint32_t sbuf,
        const __nv_bfloat16* __restrict__ Ah, const __nv_bfloat16* __restrict__ Al,
        const __nv_bfloat16* __restrict__ uh, const __nv_bfloat16* __restrict__ ul,
        int l0, int k0, int tid)
{
    // A tiles: 32 k-rows x 64 l (128B rows, 8 chunks), swizzle c ^ (k&7)
    {
        int r = tid >> 3, c = tid & 7;
        uint32_t off = (uint32_t)r * 128 + ((uint32_t)(c ^ (r & 7)) << 4);
        cp16(sbuf + off,             Ah + (size_t)(k0 + r) * L_ + l0 + c * 8);
        cp16(sbuf + IT_AL_OFF + off, Al + (size_t)(k0 + r) * L_ + l0 + c * 8);
        cp16(sbuf + IT_UH_OFF + off, uh + (size_t)(k0 + r) * N_ + c * 8);
        cp16(sbuf + IT_UL_OFF + off, ul + (size_t)(k0 + r) * N_ + c * 8);
    }
    asm volatile("cp.async.commit_group;" ::: "memory");
}

template<int LAST>
__global__ __launch_bounds__(256, 2)
void iter_mma(const __nv_bfloat16* __restrict__ Ah, const __nv_bfloat16* __restrict__ Al,
              const __nv_bfloat16* __restrict__ uh_in, const __nv_bfloat16* __restrict__ ul_in,
              const float* __restrict__ B0, const float* __restrict__ pred,
              __nv_bfloat16* __restrict__ uh_out, __nv_bfloat16* __restrict__ ul_out,
              float* __restrict__ f32out)
{
    extern __shared__ __align__(1024) char smem[];
    const uint32_t sb = smem_u32(smem);
    const int tid = threadIdx.x;
    const int b = blockIdx.z;
    const int l0 = blockIdx.x * 64;

    const __nv_bfloat16* Ahb = Ah + (size_t)b * L_ * L_;
    const __nv_bfloat16* Alb = Al + (size_t)b * L_ * L_;
    const __nv_bfloat16* uhb = uh_in + (size_t)b * L_ * N_;
    const __nv_bfloat16* ulb = ul_in + (size_t)b * L_ * N_;

    const int lane = tid & 31, warp = tid >> 5;
    const int wm = warp >> 2, wn = warp & 3;   // warp tile: 32 l x 16 n

    // A-op (trans) addresses: k = ks*16 + (lane&7) + ((lane>>4)<<3),
    // chunk cA = wm*4 + am*2 + ((lane>>3)&1)   (8 chunks per 128B row)
    uint32_t aoff[2][2];
    {
        uint32_t k_lane = (uint32_t)((lane & 7) + ((lane >> 4) << 3));
        uint32_t mbit = (uint32_t)((lane >> 3) & 1);
        #pragma unroll
        for (int ks = 0; ks < 2; ks++) {
            uint32_t k = (uint32_t)(ks * 16) + k_lane;
            #pragma unroll
            for (int am = 0; am < 2; am++) {
                uint32_t cA = (uint32_t)(wm * 4 + am * 2) + mbit;
                aoff[ks][am] = k * 128 + ((cA ^ (k & 7)) << 4);
            }
        }
    }
    uint32_t uoff[2];
    {
        uint32_t k_lane = (uint32_t)((lane & 7) + (((lane >> 3) & 1) << 3));
        uint32_t cn = (uint32_t)(wn * 2 + (lane >> 4));
        #pragma unroll
        for (int ks = 0; ks < 2; ks++) {
            uint32_t k = (uint32_t)(ks * 16) + k_lane;
            uoff[ks] = k * 128 + ((cn ^ (k & 7)) << 4);
        }
    }

    float acc[2][2][4];
    #pragma unroll
    for (int i = 0; i < 2; i++)
        #pragma unroll
        for (int j = 0; j < 2; j++)
            #pragma unroll
            for (int q = 0; q < 4; q++) acc[i][j][q] = 0.0f;

    const int NS = L_ / IT_KC;   // 32
    it_stage(sb + 0 * IT_STG, Ahb, Alb, uhb, ulb, l0, 0,      tid);
    it_stage(sb + 1 * IT_STG, Ahb, Alb, uhb, ulb, l0, IT_KC,  tid);

    int buf = 0;
    for (int st = 0; st < NS; st++) {
        if (st + 1 < NS) asm volatile("cp.async.wait_group 1;" ::: "memory");
        else             asm volatile("cp.async.wait_group 0;" ::: "memory");
        __syncthreads();

        const uint32_t sbuf = sb + (uint32_t)buf * IT_STG;
        #pragma unroll
        for (int ks = 0; ks < 2; ks++) {
            uint32_t ah[2][4], al4[2][4];
            #pragma unroll
            for (int am = 0; am < 2; am++) {
                ldsm4t(sbuf + aoff[ks][am],
                       ah[am][0], ah[am][1], ah[am][2], ah[am][3]);
                ldsm4t(sbuf + IT_AL_OFF + aoff[ks][am],
                       al4[am][0], al4[am][1], al4[am][2], al4[am][3]);
            }
            uint32_t bh[2][2], bl[2][2];
            {
                uint32_t r0, r1, r2, r3;
                ldsm4t(sbuf + IT_UH_OFF + uoff[ks], r0, r1, r2, r3);
                bh[0][0] = r0; bh[0][1] = r1; bh[1][0] = r2; bh[1][1] = r3;
                ldsm4t(sbuf + IT_UL_OFF + uoff[ks], r0, r1, r2, r3);
                bl[0][0] = r0; bl[0][1] = r1; bl[1][0] = r2; bl[1][1] = r3;
            }
            #pragma unroll
            for (int am = 0; am < 2; am++)
                #pragma unroll
                for (int an = 0; an < 2; an++)
                    mma16816(acc[am][an], ah[am], bh[an]);
            #pragma unroll
            for (int am = 0; am < 2; am++)
                #pragma unroll
                for (int an = 0; an < 2; an++)
                    mma16816(acc[am][an], ah[am], bl[an]);
            #pragma unroll
            for (int am = 0; am < 2; am++)
                #pragma unroll
                for (int an = 0; an < 2; an++)
                    mma16816(acc[am][an], al4[am], bh[an]);
        }

        if (st + 2 < NS) {
            int nb = buf + 2; if (nb >= 3) nb -= 3;
            it_stage(sb + (uint32_t)nb * IT_STG, Ahb, Alb, uhb, ulb,
                     l0, (st + 2) * IT_KC, tid);
        }
        if (++buf == 3) buf = 0;
    }

    const int lbase = l0 + wm * 32 + (lane >> 2);
    const int nbase = wn * 16 + (lane & 3) * 2;
    #pragma unroll
    for (int am = 0; am < 2; am++) {
        #pragma unroll
        for (int an = 0; an < 2; an++) {
            const int l = lbase + am * 16;
            const int n = nbase + an * 8;
            const size_t o0 = ((size_t)b * L_ + l) * N_ + n;
            const size_t o1 = o0 + 8 * N_;
            float v0 = acc[am][an][0] + B0[o0];
            float v1 = acc[am][an][1] + B0[o0 + 1];
            float v2 = acc[am][an][2] + B0[o1];
            float v3 = acc[am][an][3] + B0[o1 + 1];
            if (pred) {
                v0 += pred[o0]; v1 += pred[o0 + 1];
                v2 += pred[o1]; v3 += pred[o1 + 1];
            }
            if (LAST) {
                *(float2*)&f32out[o0] = make_float2(v0, v1);
                *(float2*)&f32out[o1] = make_float2(v2, v3);
            } else {
                __nv_bfloat16 h0 = __float2bfloat16(v0), h1 = __float2bfloat16(v1);
                __nv_bfloat16 h2 = __float2bfloat16(v2), h3 = __float2bfloat16(v3);
                __nv_bfloat162 lo01 = __floats2bfloat162_rn(v0 - __bfloat162float(h0),
                                                            v1 - __bfloat162float(h1));
                __nv_bfloat162 lo23 = __floats2bfloat162_rn(v2 - __bfloat162float(h2),
                                                            v3 - __bfloat162float(h3));
                uint32_t hp0 = (uint32_t)__bfloat16_as_ushort(h0) |
                               ((uint32_t)__bfloat16_as_ushort(h1) << 16);
                uint32_t hp1 = (uint32_t)__bfloat16_as_ushort(h2) |
                               ((uint32_t)__bfloat16_as_ushort(h3) << 16);
                *(uint32_t*)&uh_out[o0] = hp0;
                *(uint32_t*)&uh_out[o1] = hp1;
                *(uint32_t*)&ul_out[o0] = *reinterpret_cast<uint32_t*>(&lo01);
                *(uint32_t*)&ul_out[o1] = *reinterpret_cast<uint32_t*>(&lo23);
            }
        }
    }
}

// ---------------------------------------------------------------------------
extern "C" void kernel_launch(void* const* d_in, const int* in_sizes, int n_in,
                              void* d_out, int out_size)
{
    const float* samples = (const float*)d_in[0];  // [8,1024,3072]
    const float* label   = (const float*)d_in[1];  // [8,1024,64]
    const float* predict = (const float*)d_in[2];  // [8,1024,64]
    const float* W       = (const float*)d_in[3];  // [1024,3072]
    const float* bproj   = (const float*)d_in[4];  // [1024]
    float* out = (float*)d_out;                    // [8,1024,64]

    __nv_bfloat16 *smph, *smpl, *Wh, *Wl, *sh, *sl, *uh1, *ul1, *uh2, *ul2;
    float *A, *B0;
    cudaGetSymbolAddress((void**)&smph, g_smp_hi);
    cudaGetSymbolAddress((void**)&smpl, g_smp_lo);
    cudaGetSymbolAddress((void**)&Wh,   g_W_hi);
    cudaGetSymbolAddress((void**)&Wl,   g_W_lo);
    cudaGetSymbolAddress((void**)&sh,   g_s_hi);
    cudaGetSymbolAddress((void**)&sl,   g_s_lo);
    cudaGetSymbolAddress((void**)&A,    g_A);
    cudaGetSymbolAddress((void**)&B0,   g_B0);
    cudaGetSymbolAddress((void**)&uh1,  g_uh1);
    cudaGetSymbolAddress((void**)&ul1,  g_ul1);
    cudaGetSymbolAddress((void**)&uh2,  g_uh2);
    cudaGetSymbolAddress((void**)&ul2,  g_ul2);

    cudaFuncSetAttribute(gemm_proj, cudaFuncAttributeMaxDynamicSharedMemorySize, P_SMEM);
    cudaFuncSetAttribute(gemm_sym,  cudaFuncAttributeMaxDynamicSharedMemorySize, S_SMEM);
    cudaFuncSetAttribute(iter_mma<0>, cudaFuncAttributeMaxDynamicSharedMemorySize, IT_SMEM);
    cudaFuncSetAttribute(iter_mma<1>, cudaFuncAttributeMaxDynamicSharedMemorySize, IT_SMEM);

    {
        int n4 = (B_ * L_ * K3_) / 4;
        split_kernel<<<(n4 + 255) / 256, 256>>>(samples, smph, smpl, n4);
        int w4 = (H_ * K3_) / 4;
        split_kernel<<<(w4 + 255) / 256, 256>>>(W, Wh, Wl, w4);
    }

    gemm_proj<<<dim3(H_ / 256, (B_ * L_) / 128, 1), 256, P_SMEM>>>(
        smph, smpl, Wh, Wl, bproj, sh, sl);

    gemm_sym<<<dim3(36, 1, B_), 256, S_SMEM>>>(sh, sl, A);

    softmax_kernel<<<dim3(L_, B_), 256>>>(A, sh, sl);

    b0_kernel<<<B_, 1024>>>(label, B0, uh1, ul1);

    dim3 ig(L_ / 64, 1, B_);   // 128 CTAs — near-full single wave
    iter_mma<0><<<ig, 256, IT_SMEM>>>(sh, sl, uh1, ul1, B0, nullptr,  uh2, ul2, nullptr); // t=2
    iter_mma<0><<<ig, 256, IT_SMEM>>>(sh, sl, uh2, ul2, B0, predict,  uh1, ul1, nullptr); // t=3
    iter_mma<0><<<ig, 256, IT_SMEM>>>(sh, sl, uh1, ul1, B0, nullptr,  uh2, ul2, nullptr); // t=4
    iter_mma<0><<<ig, 256, IT_SMEM>>>(sh, sl, uh2, ul2, B0, nullptr,  uh1, ul1, nullptr); // t=5
    iter_mma<1><<<ig, 256, IT_SMEM>>>(sh, sl, uh1, ul1, B0, nullptr,  nullptr, nullptr, out); // t=6
}